// round 1
// baseline (speedup 1.0000x reference)
#include <cuda_runtime.h>
#include <cuda_bf16.h>

#define DINLINE __device__ __forceinline__

// Problem constants
constexpr int B_  = 2;
constexpr int S_  = 2048;
constexpr int D_  = 1024;
constexpr int H_  = 16;
constexpr int DK_ = 64;

// Scratch (device globals: no allocation allowed)
__device__ float g_q[(size_t)B_ * H_ * S_ * DK_];
__device__ float g_k[(size_t)B_ * H_ * S_ * DK_];
__device__ float g_v[(size_t)B_ * H_ * S_ * DK_];
__device__ float g_ctx[(size_t)B_ * S_ * D_];

DINLINE unsigned packh(__nv_bfloat16 a, __nv_bfloat16 b) {
    __nv_bfloat162 v; v.x = a; v.y = b;
    return *reinterpret_cast<unsigned*>(&v);
}

// split a float into hi/lo bf16 halves
DINLINE void splitf(float x, __nv_bfloat16& h, __nv_bfloat16& l) {
    h = __float2bfloat16(x);
    l = __float2bfloat16(x - __bfloat162float(h));
}

DINLINE void mma16816(float* c, const unsigned* a, unsigned b0, unsigned b1) {
    asm volatile(
        "mma.sync.aligned.m16n8k16.row.col.f32.bf16.bf16.f32 "
        "{%0,%1,%2,%3},{%4,%5,%6,%7},{%8,%9},{%0,%1,%2,%3};\n"
        : "+f"(c[0]), "+f"(c[1]), "+f"(c[2]), "+f"(c[3])
        : "r"(a[0]), "r"(a[1]), "r"(a[2]), "r"(a[3]), "r"(b0), "r"(b1));
}

// ============================================================================
// GEMM: Y[4096,1024] = X[4096,1024] @ W^T[1024,1024] + bias
// MODE 0: write to [B,H,S,DK] layout (projection).  MODE 1: plain [M,N].
// bf16 split: acc += Ah*Bh + Ah*Bl + Al*Bh  (fp32 accumulate)
// Block: 128 threads (2x2 warps, each 32x32), tile 64x64, K-step 32.
// ============================================================================
template<int MODE>
__global__ void __launch_bounds__(128) gemm_kernel(
    const float* __restrict__ X, const float* __restrict__ W,
    const float* __restrict__ bias, float* __restrict__ Y)
{
    constexpr int LD = 40;  // 32 + 8 pad: conflict-free frag loads
    __shared__ __nv_bfloat16 sAh[64 * LD], sAl[64 * LD];
    __shared__ __nv_bfloat16 sBh[64 * LD], sBl[64 * LD];

    const int t    = threadIdx.x;
    const int w    = t >> 5;
    const int lane = t & 31;
    const int g    = lane >> 2;   // group id (0..7)
    const int tg   = lane & 3;    // thread-in-group
    const int wm   = w >> 1;      // warp row (0..1)
    const int wn   = w & 1;       // warp col (0..1)
    const int m0   = blockIdx.y * 64;
    const int n0   = blockIdx.x * 64;

    float acc[2][4][4];
#pragma unroll
    for (int mi = 0; mi < 2; mi++)
#pragma unroll
        for (int ni = 0; ni < 4; ni++)
#pragma unroll
            for (int j = 0; j < 4; j++) acc[mi][ni][j] = 0.f;

    for (int kt = 0; kt < 1024; kt += 32) {
#pragma unroll
        for (int i = 0; i < 16; i++) {
            int e = t + i * 128;
            int r = e >> 5, c = e & 31;
            float xv = X[(size_t)(m0 + r) * 1024 + kt + c];
            __nv_bfloat16 h, l;
            splitf(xv, h, l);
            sAh[r * LD + c] = h; sAl[r * LD + c] = l;
            float wv = W[(size_t)(n0 + r) * 1024 + kt + c];
            splitf(wv, h, l);
            sBh[r * LD + c] = h; sBl[r * LD + c] = l;
        }
        __syncthreads();

#pragma unroll
        for (int kk = 0; kk < 32; kk += 16) {
            unsigned ah[2][4], al[2][4];
#pragma unroll
            for (int mi = 0; mi < 2; mi++) {
                int r = wm * 32 + mi * 16 + g;
                int c = kk + tg * 2;
                ah[mi][0] = *(const unsigned*)&sAh[r * LD + c];
                ah[mi][1] = *(const unsigned*)&sAh[(r + 8) * LD + c];
                ah[mi][2] = *(const unsigned*)&sAh[r * LD + c + 8];
                ah[mi][3] = *(const unsigned*)&sAh[(r + 8) * LD + c + 8];
                al[mi][0] = *(const unsigned*)&sAl[r * LD + c];
                al[mi][1] = *(const unsigned*)&sAl[(r + 8) * LD + c];
                al[mi][2] = *(const unsigned*)&sAl[r * LD + c + 8];
                al[mi][3] = *(const unsigned*)&sAl[(r + 8) * LD + c + 8];
            }
#pragma unroll
            for (int ni = 0; ni < 4; ni++) {
                int n = wn * 32 + ni * 8 + g;
                int c = kk + tg * 2;
                unsigned bh0 = *(const unsigned*)&sBh[n * LD + c];
                unsigned bh1 = *(const unsigned*)&sBh[n * LD + c + 8];
                unsigned bl0 = *(const unsigned*)&sBl[n * LD + c];
                unsigned bl1 = *(const unsigned*)&sBl[n * LD + c + 8];
#pragma unroll
                for (int mi = 0; mi < 2; mi++) {
                    mma16816(acc[mi][ni], ah[mi], bh0, bh1);
                    mma16816(acc[mi][ni], ah[mi], bl0, bl1);
                    mma16816(acc[mi][ni], al[mi], bh0, bh1);
                }
            }
        }
        __syncthreads();
    }

    // Epilogue
#pragma unroll
    for (int mi = 0; mi < 2; mi++) {
#pragma unroll
        for (int ni = 0; ni < 4; ni++) {
            int r = m0 + wm * 32 + mi * 16 + g;
            int c = n0 + wn * 32 + ni * 8 + tg * 2;
            float b0 = bias[c], b1 = bias[c + 1];
            float v00 = acc[mi][ni][0] + b0;
            float v01 = acc[mi][ni][1] + b1;
            float v10 = acc[mi][ni][2] + b0;
            float v11 = acc[mi][ni][3] + b1;
            if (MODE == 0) {
                // [BS, D] -> [B, H, S, DK]
                int bb = r >> 11, s = r & 2047;
                int hh = c >> 6, d = c & 63;
                size_t base0 = ((size_t)(bb * H_ + hh) * S_ + s) * DK_ + d;
                size_t base1 = ((size_t)(bb * H_ + hh) * S_ + (s + 8)) * DK_ + d;
                Y[base0] = v00; Y[base0 + 1] = v01;
                Y[base1] = v10; Y[base1 + 1] = v11;
            } else {
                Y[(size_t)r * 1024 + c] = v00;
                Y[(size_t)r * 1024 + c + 1] = v01;
                Y[(size_t)(r + 8) * 1024 + c] = v10;
                Y[(size_t)(r + 8) * 1024 + c + 1] = v11;
            }
        }
    }
}

// ============================================================================
// Flash attention (causal), DK=64.
// Grid: (S/64 q-tiles, B*H). Block: 128 threads = 4 warps, warp w owns q rows
// [qt*64 + w*16, +16). Q fragments register-resident (hi/lo bf16 split).
// K tile smem [kv][dk], V tile transposed [dk][kv]; stride 72 (conflict-free).
// ============================================================================
__global__ void __launch_bounds__(128, 1) attn_kernel(
    const float* __restrict__ Q, const float* __restrict__ K,
    const float* __restrict__ V, float* __restrict__ ctx)
{
    constexpr int LD = 72;
    __shared__ __nv_bfloat16 sKh[64 * LD], sKl[64 * LD];
    __shared__ __nv_bfloat16 sVh[64 * LD], sVl[64 * LD];

    const int qt   = blockIdx.x;
    const int bh   = blockIdx.y;
    const int t    = threadIdx.x;
    const int w    = t >> 5;
    const int lane = t & 31;
    const int g    = lane >> 2;
    const int tg   = lane & 3;

    const float* Qb = Q + ((size_t)bh * S_) * DK_;
    const float* Kb = K + ((size_t)bh * S_) * DK_;
    const float* Vb = V + ((size_t)bh * S_) * DK_;

    const float NEG = -1e30f;

    // ---- stage Q tile into sKh/sKl, then load register fragments ----
#pragma unroll
    for (int i = 0; i < 32; i++) {
        int e = t + i * 128;
        int r = e >> 6, c = e & 63;
        float x = Qb[(size_t)(qt * 64 + r) * DK_ + c];
        __nv_bfloat16 h, l;
        splitf(x, h, l);
        sKh[r * LD + c] = h; sKl[r * LD + c] = l;
    }
    __syncthreads();

    unsigned qh[4][4], ql[4][4];
    {
        int r = w * 16 + g;
#pragma unroll
        for (int kk = 0; kk < 4; kk++) {
            int c = kk * 16 + tg * 2;
            qh[kk][0] = *(const unsigned*)&sKh[r * LD + c];
            qh[kk][1] = *(const unsigned*)&sKh[(r + 8) * LD + c];
            qh[kk][2] = *(const unsigned*)&sKh[r * LD + c + 8];
            qh[kk][3] = *(const unsigned*)&sKh[(r + 8) * LD + c + 8];
            ql[kk][0] = *(const unsigned*)&sKl[r * LD + c];
            ql[kk][1] = *(const unsigned*)&sKl[(r + 8) * LD + c];
            ql[kk][2] = *(const unsigned*)&sKl[r * LD + c + 8];
            ql[kk][3] = *(const unsigned*)&sKl[(r + 8) * LD + c + 8];
        }
    }

    float m0v = NEG, m1v = NEG, l0v = 0.f, l1v = 0.f;
    float o[8][4];
#pragma unroll
    for (int ni = 0; ni < 8; ni++)
#pragma unroll
        for (int j = 0; j < 4; j++) o[ni][j] = 0.f;

    for (int kt = 0; kt <= qt; kt++) {
        __syncthreads();  // previous iteration's (or Q frag) smem reads done
        // ---- load K tile [kv][dk] and V tile transposed [dk][kv] ----
#pragma unroll
        for (int i = 0; i < 32; i++) {
            int e = t + i * 128;
            int r = e >> 6, c = e & 63;
            float kv = Kb[(size_t)(kt * 64 + r) * DK_ + c];
            __nv_bfloat16 h, l;
            splitf(kv, h, l);
            sKh[r * LD + c] = h; sKl[r * LD + c] = l;
            float vv = Vb[(size_t)(kt * 64 + r) * DK_ + c];
            splitf(vv, h, l);
            sVh[c * LD + r] = h; sVl[c * LD + r] = l;  // transposed store
        }
        __syncthreads();

        // ---- S = Q K^T (16x64 per warp) ----
        float s[8][4];
#pragma unroll
        for (int ni = 0; ni < 8; ni++)
#pragma unroll
            for (int j = 0; j < 4; j++) s[ni][j] = 0.f;

#pragma unroll
        for (int ni = 0; ni < 8; ni++) {
#pragma unroll
            for (int kk = 0; kk < 4; kk++) {
                int off = (ni * 8 + g) * LD + kk * 16 + tg * 2;
                unsigned kh0 = *(const unsigned*)&sKh[off];
                unsigned kh1 = *(const unsigned*)&sKh[off + 8];
                unsigned kl0 = *(const unsigned*)&sKl[off];
                unsigned kl1 = *(const unsigned*)&sKl[off + 8];
                mma16816(s[ni], qh[kk], kh0, kh1);
                mma16816(s[ni], qh[kk], kl0, kl1);
                mma16816(s[ni], ql[kk], kh0, kh1);
            }
        }

        // ---- scale + causal mask ----
        const float sc = 0.125f;  // 1/sqrt(64)
        if (kt == qt) {
            int rA = w * 16 + g, rB = rA + 8;
#pragma unroll
            for (int ni = 0; ni < 8; ni++) {
                int c0 = ni * 8 + tg * 2;
                s[ni][0] = (c0     > rA) ? NEG : s[ni][0] * sc;
                s[ni][1] = (c0 + 1 > rA) ? NEG : s[ni][1] * sc;
                s[ni][2] = (c0     > rB) ? NEG : s[ni][2] * sc;
                s[ni][3] = (c0 + 1 > rB) ? NEG : s[ni][3] * sc;
            }
        } else {
#pragma unroll
            for (int ni = 0; ni < 8; ni++)
#pragma unroll
                for (int j = 0; j < 4; j++) s[ni][j] *= sc;
        }

        // ---- streaming softmax ----
        float mx0 = NEG, mx1 = NEG;
#pragma unroll
        for (int ni = 0; ni < 8; ni++) {
            mx0 = fmaxf(mx0, fmaxf(s[ni][0], s[ni][1]));
            mx1 = fmaxf(mx1, fmaxf(s[ni][2], s[ni][3]));
        }
        mx0 = fmaxf(mx0, __shfl_xor_sync(0xffffffffu, mx0, 1));
        mx0 = fmaxf(mx0, __shfl_xor_sync(0xffffffffu, mx0, 2));
        mx1 = fmaxf(mx1, __shfl_xor_sync(0xffffffffu, mx1, 1));
        mx1 = fmaxf(mx1, __shfl_xor_sync(0xffffffffu, mx1, 2));

        float nm0 = fmaxf(m0v, mx0), nm1 = fmaxf(m1v, mx1);
        float corr0 = __expf(m0v - nm0), corr1 = __expf(m1v - nm1);

        float sum0 = 0.f, sum1 = 0.f;
#pragma unroll
        for (int ni = 0; ni < 8; ni++) {
            s[ni][0] = __expf(s[ni][0] - nm0);
            s[ni][1] = __expf(s[ni][1] - nm0);
            s[ni][2] = __expf(s[ni][2] - nm1);
            s[ni][3] = __expf(s[ni][3] - nm1);
            sum0 += s[ni][0] + s[ni][1];
            sum1 += s[ni][2] + s[ni][3];
        }
        sum0 += __shfl_xor_sync(0xffffffffu, sum0, 1);
        sum0 += __shfl_xor_sync(0xffffffffu, sum0, 2);
        sum1 += __shfl_xor_sync(0xffffffffu, sum1, 1);
        sum1 += __shfl_xor_sync(0xffffffffu, sum1, 2);

        l0v = l0v * corr0 + sum0;
        l1v = l1v * corr1 + sum1;
        m0v = nm0; m1v = nm1;

#pragma unroll
        for (int ni = 0; ni < 8; ni++) {
            o[ni][0] *= corr0; o[ni][1] *= corr0;
            o[ni][2] *= corr1; o[ni][3] *= corr1;
        }

        // ---- O += P V  (P hi/lo split, A-frag == C-frag layout) ----
#pragma unroll
        for (int j = 0; j < 4; j++) {
            unsigned ah[4], al[4];
            {
                __nv_bfloat16 h0, l0, h1, l1;
                splitf(s[2 * j][0], h0, l0); splitf(s[2 * j][1], h1, l1);
                ah[0] = packh(h0, h1); al[0] = packh(l0, l1);
                splitf(s[2 * j][2], h0, l0); splitf(s[2 * j][3], h1, l1);
                ah[1] = packh(h0, h1); al[1] = packh(l0, l1);
                splitf(s[2 * j + 1][0], h0, l0); splitf(s[2 * j + 1][1], h1, l1);
                ah[2] = packh(h0, h1); al[2] = packh(l0, l1);
                splitf(s[2 * j + 1][2], h0, l0); splitf(s[2 * j + 1][3], h1, l1);
                ah[3] = packh(h0, h1); al[3] = packh(l0, l1);
            }
#pragma unroll
            for (int ni = 0; ni < 8; ni++) {
                int off = (ni * 8 + g) * LD + j * 16 + tg * 2;
                unsigned vh0 = *(const unsigned*)&sVh[off];
                unsigned vh1 = *(const unsigned*)&sVh[off + 8];
                unsigned vl0 = *(const unsigned*)&sVl[off];
                unsigned vl1 = *(const unsigned*)&sVl[off + 8];
                mma16816(o[ni], ah, vh0, vh1);
                mma16816(o[ni], ah, vl0, vl1);
                mma16816(o[ni], al, vh0, vh1);
            }
        }
    }

    // ---- finalize: divide by l, write ctx [B,S,D] ----
    float inv0 = 1.f / l0v, inv1 = 1.f / l1v;
    int bb = bh >> 4, hh = bh & 15;
    int q0 = qt * 64 + w * 16 + g;
#pragma unroll
    for (int ni = 0; ni < 8; ni++) {
        int d = ni * 8 + tg * 2;
        size_t i0 = ((size_t)(bb * S_ + q0)) * D_ + hh * 64 + d;
        size_t i1 = ((size_t)(bb * S_ + q0 + 8)) * D_ + hh * 64 + d;
        ctx[i0]     = o[ni][0] * inv0;
        ctx[i0 + 1] = o[ni][1] * inv0;
        ctx[i1]     = o[ni][2] * inv1;
        ctx[i1 + 1] = o[ni][3] * inv1;
    }
}

// ============================================================================
// Launch
// ============================================================================
extern "C" void kernel_launch(void* const* d_in, const int* in_sizes, int n_in,
                              void* d_out, int out_size)
{
    const float* q   = (const float*)d_in[0];
    const float* k   = (const float*)d_in[1];
    const float* v   = (const float*)d_in[2];
    // d_in[3] = mask (causal tril; handled analytically)
    const float* wq = (const float*)d_in[4];
    const float* bq = (const float*)d_in[5];
    const float* wk = (const float*)d_in[6];
    const float* bk = (const float*)d_in[7];
    const float* wv = (const float*)d_in[8];
    const float* bv = (const float*)d_in[9];
    const float* wo = (const float*)d_in[10];
    const float* bo = (const float*)d_in[11];
    float* out = (float*)d_out;

    float *gq, *gk, *gv, *gctx;
    cudaGetSymbolAddress((void**)&gq, g_q);
    cudaGetSymbolAddress((void**)&gk, g_k);
    cudaGetSymbolAddress((void**)&gv, g_v);
    cudaGetSymbolAddress((void**)&gctx, g_ctx);

    dim3 gg(1024 / 64, (B_ * S_) / 64);  // (16, 64)
    gemm_kernel<0><<<gg, 128>>>(q, wq, bq, gq);
    gemm_kernel<0><<<gg, 128>>>(k, wk, bk, gk);
    gemm_kernel<0><<<gg, 128>>>(v, wv, bv, gv);

    attn_kernel<<<dim3(S_ / 64, B_ * H_), 128>>>(gq, gk, gv, gctx);

    gemm_kernel<1><<<gg, 128>>>(gctx, wo, bo, out);
}

// round 2
// speedup vs baseline: 1.3132x; 1.3132x over previous
#include <cuda_runtime.h>
#include <cuda_bf16.h>

#define DINLINE __device__ __forceinline__

constexpr int B_  = 2;
constexpr int S_  = 2048;
constexpr int D_  = 1024;
constexpr int H_  = 16;
constexpr int DK_ = 64;

constexpr size_t NQKV = (size_t)B_ * H_ * S_ * DK_;  // 4M elems per tensor

// Scratch: Q/K/V as packed bf16 hi/lo ([3][B,H,S,DK]), ctx as f32
__device__ __nv_bfloat16 g_h[3 * NQKV];
__device__ __nv_bfloat16 g_l[3 * NQKV];
__device__ float g_ctx[(size_t)B_ * S_ * D_];

DINLINE unsigned packh(__nv_bfloat16 a, __nv_bfloat16 b) {
    __nv_bfloat162 v; v.x = a; v.y = b;
    return *reinterpret_cast<unsigned*>(&v);
}
DINLINE void splitf(float x, __nv_bfloat16& h, __nv_bfloat16& l) {
    h = __float2bfloat16(x);
    l = __float2bfloat16(x - __bfloat162float(h));
}
DINLINE void mma16816(float* c, const unsigned* a, unsigned b0, unsigned b1) {
    asm volatile(
        "mma.sync.aligned.m16n8k16.row.col.f32.bf16.bf16.f32 "
        "{%0,%1,%2,%3},{%4,%5,%6,%7},{%8,%9},{%0,%1,%2,%3};\n"
        : "+f"(c[0]), "+f"(c[1]), "+f"(c[2]), "+f"(c[3])
        : "r"(a[0]), "r"(a[1]), "r"(a[2]), "r"(a[3]), "r"(b0), "r"(b1));
}
DINLINE unsigned smem_u32(const void* p) {
    unsigned a;
    asm("{.reg .u64 t; cvta.to.shared.u64 t, %1; cvt.u32.u64 %0, t;}" : "=r"(a) : "l"(p));
    return a;
}
#define CP_ASYNC16(dst, src) \
    asm volatile("cp.async.ca.shared.global [%0], [%1], 16;\n" :: "r"(dst), "l"(src))
#define CP_COMMIT()  asm volatile("cp.async.commit_group;\n")
#define CP_WAIT0()   asm volatile("cp.async.wait_group 0;\n")

// ============================================================================
// GEMM: Y[4096,1024] = X @ W^T + b.  Tile 128x128, 256 threads, BK=32,
// register-prefetch pipeline, 3-term bf16 split.
// MODE 0: z in {0,1,2} selects (X,W,b); writes hi/lo bf16 [B,H,S,DK] scratch.
// MODE 1: f32 out [M,N].
// ============================================================================
template<int MODE>
__global__ void __launch_bounds__(256) gemm_kernel(
    const float* __restrict__ X0, const float* __restrict__ X1, const float* __restrict__ X2,
    const float* __restrict__ W0, const float* __restrict__ bias0,
    const float* __restrict__ W1, const float* __restrict__ bias1,
    const float* __restrict__ W2, const float* __restrict__ bias2,
    __nv_bfloat16* __restrict__ Yh, __nv_bfloat16* __restrict__ Yl,
    float* __restrict__ Yf)
{
    constexpr int LD = 40;  // 32 + 8 pad, conflict-free frag loads
    __shared__ __nv_bfloat16 sAh[128 * LD], sAl[128 * LD];
    __shared__ __nv_bfloat16 sBh[128 * LD], sBl[128 * LD];

    const int z = (MODE == 0) ? blockIdx.z : 0;
    const float* X    = (MODE == 1) ? X0 : (z == 0 ? X0 : (z == 1 ? X1 : X2));
    const float* W    = (z == 0) ? W0 : (z == 1 ? W1 : W2);
    const float* bias = (z == 0) ? bias0 : (z == 1 ? bias1 : bias2);

    const int t    = threadIdx.x;
    const int w    = t >> 5;
    const int lane = t & 31;
    const int g    = lane >> 2;
    const int tg   = lane & 3;
    const int wm   = w >> 1;   // 0..3 -> m offset *32
    const int wn   = w & 1;    // 0..1 -> n offset *64
    const int m0   = blockIdx.y * 128;
    const int n0   = blockIdx.x * 128;

    const int lrow = t >> 3;   // 0..31 load row base
    const int lc4  = t & 7;    // float4 column

    float acc[2][8][4];
#pragma unroll
    for (int mi = 0; mi < 2; mi++)
#pragma unroll
        for (int ni = 0; ni < 8; ni++)
#pragma unroll
            for (int j = 0; j < 4; j++) acc[mi][ni][j] = 0.f;

    float4 pa[4], pb[4];
    auto load_slab = [&](int kt) {
#pragma unroll
        for (int i = 0; i < 4; i++) {
            int row = lrow + i * 32;
            pa[i] = *(const float4*)&X[(size_t)(m0 + row) * 1024 + kt * 32 + lc4 * 4];
            pb[i] = *(const float4*)&W[(size_t)(n0 + row) * 1024 + kt * 32 + lc4 * 4];
        }
    };
    auto store_slab = [&]() {
#pragma unroll
        for (int i = 0; i < 4; i++) {
            int row = lrow + i * 32;
            int c   = lc4 * 4;
            __nv_bfloat16 h0, l0, h1, l1, h2, l2, h3, l3;
            splitf(pa[i].x, h0, l0); splitf(pa[i].y, h1, l1);
            splitf(pa[i].z, h2, l2); splitf(pa[i].w, h3, l3);
            uint2 uh = { packh(h0, h1), packh(h2, h3) };
            uint2 ul = { packh(l0, l1), packh(l2, l3) };
            *(uint2*)&sAh[row * LD + c] = uh;
            *(uint2*)&sAl[row * LD + c] = ul;
            splitf(pb[i].x, h0, l0); splitf(pb[i].y, h1, l1);
            splitf(pb[i].z, h2, l2); splitf(pb[i].w, h3, l3);
            uh = { packh(h0, h1), packh(h2, h3) };
            ul = { packh(l0, l1), packh(l2, l3) };
            *(uint2*)&sBh[row * LD + c] = uh;
            *(uint2*)&sBl[row * LD + c] = ul;
        }
    };

    load_slab(0);
    for (int kt = 0; kt < 32; kt++) {
        store_slab();
        __syncthreads();
        if (kt + 1 < 32) load_slab(kt + 1);
#pragma unroll
        for (int kk = 0; kk < 32; kk += 16) {
            unsigned ah[2][4], al[2][4];
#pragma unroll
            for (int mi = 0; mi < 2; mi++) {
                int r = wm * 32 + mi * 16 + g;
                int c = kk + tg * 2;
                ah[mi][0] = *(const unsigned*)&sAh[r * LD + c];
                ah[mi][1] = *(const unsigned*)&sAh[(r + 8) * LD + c];
                ah[mi][2] = *(const unsigned*)&sAh[r * LD + c + 8];
                ah[mi][3] = *(const unsigned*)&sAh[(r + 8) * LD + c + 8];
                al[mi][0] = *(const unsigned*)&sAl[r * LD + c];
                al[mi][1] = *(const unsigned*)&sAl[(r + 8) * LD + c];
                al[mi][2] = *(const unsigned*)&sAl[r * LD + c + 8];
                al[mi][3] = *(const unsigned*)&sAl[(r + 8) * LD + c + 8];
            }
#pragma unroll
            for (int ni = 0; ni < 8; ni++) {
                int n = wn * 64 + ni * 8 + g;
                int c = kk + tg * 2;
                unsigned bh0 = *(const unsigned*)&sBh[n * LD + c];
                unsigned bh1 = *(const unsigned*)&sBh[n * LD + c + 8];
                unsigned bl0 = *(const unsigned*)&sBl[n * LD + c];
                unsigned bl1 = *(const unsigned*)&sBl[n * LD + c + 8];
#pragma unroll
                for (int mi = 0; mi < 2; mi++) {
                    mma16816(acc[mi][ni], ah[mi], bh0, bh1);
                    mma16816(acc[mi][ni], ah[mi], bl0, bl1);
                    mma16816(acc[mi][ni], al[mi], bh0, bh1);
                }
            }
        }
        __syncthreads();
    }

    // Epilogue
    const size_t zoff = (size_t)z * NQKV;
#pragma unroll
    for (int mi = 0; mi < 2; mi++) {
#pragma unroll
        for (int ni = 0; ni < 8; ni++) {
            int r = m0 + wm * 32 + mi * 16 + g;
            int c = n0 + wn * 64 + ni * 8 + tg * 2;
            float b0 = bias[c], b1 = bias[c + 1];
            float v00 = acc[mi][ni][0] + b0;
            float v01 = acc[mi][ni][1] + b1;
            float v10 = acc[mi][ni][2] + b0;
            float v11 = acc[mi][ni][3] + b1;
            if (MODE == 0) {
                int bb = r >> 11, s = r & 2047;
                int hh = (c >> 6) & 15, d = c & 63;
                size_t i0 = zoff + (((size_t)(bb * H_ + hh) * S_ + s)) * DK_ + d;
                size_t i1 = zoff + (((size_t)(bb * H_ + hh) * S_ + (s + 8))) * DK_ + d;
                __nv_bfloat16 h0, l0, h1, l1;
                splitf(v00, h0, l0); splitf(v01, h1, l1);
                *(unsigned*)&Yh[i0] = packh(h0, h1);
                *(unsigned*)&Yl[i0] = packh(l0, l1);
                splitf(v10, h0, l0); splitf(v11, h1, l1);
                *(unsigned*)&Yh[i1] = packh(h0, h1);
                *(unsigned*)&Yl[i1] = packh(l0, l1);
            } else {
                Yf[(size_t)r * 1024 + c]       = v00;
                Yf[(size_t)r * 1024 + c + 1]   = v01;
                Yf[(size_t)(r + 8) * 1024 + c]     = v10;
                Yf[(size_t)(r + 8) * 1024 + c + 1] = v11;
            }
        }
    }
}

// ============================================================================
// Flash attention (causal), DK=64, Q-tile 128 (8 warps x 16 rows), KV-tile 64.
// K/V already bf16 hi/lo. K streams via cp.async double buffer; V via float4
// LDG + rotated transposed STS. Q frags loaded directly from global.
// Dynamic smem: 2 stages x (Kh,Kl,Vh,Vl) x 64x72 bf16 = 73728 B.
// ============================================================================
constexpr int ALD = 72;                 // attn smem row stride (bf16)
constexpr int STAGE = 4 * 64 * ALD;     // 18432 bf16 elems per stage
constexpr int ATTN_SMEM = 2 * STAGE * 2; // bytes

__global__ void __launch_bounds__(256, 1) attn_kernel(
    const __nv_bfloat16* __restrict__ Gh, const __nv_bfloat16* __restrict__ Gl,
    float* __restrict__ ctx)
{
    extern __shared__ __nv_bfloat16 sm[];

    const int qt   = blockIdx.x;
    const int bh   = blockIdx.y;
    const int t    = threadIdx.x;
    const int w    = t >> 5;
    const int lane = t & 31;
    const int g    = lane >> 2;
    const int tg   = lane & 3;

    const size_t hb = (size_t)bh * S_ * DK_;
    const __nv_bfloat16* Qhb = Gh + hb;
    const __nv_bfloat16* Qlb = Gl + hb;
    const __nv_bfloat16* Khb = Gh + NQKV + hb;
    const __nv_bfloat16* Klb = Gl + NQKV + hb;
    const __nv_bfloat16* Vhb = Gh + 2 * NQKV + hb;
    const __nv_bfloat16* Vlb = Gl + 2 * NQKV + hb;

    const unsigned smb = smem_u32(sm);
    const float NEG = -1e30f;

    // ---- Q fragments straight from global ----
    unsigned qh[4][4], ql[4][4];
    {
        size_t r0 = (size_t)(qt * 128 + w * 16 + g) * DK_;
        size_t r1 = r0 + 8 * DK_;
#pragma unroll
        for (int kk = 0; kk < 4; kk++) {
            int c = kk * 16 + tg * 2;
            qh[kk][0] = *(const unsigned*)&Qhb[r0 + c];
            qh[kk][1] = *(const unsigned*)&Qhb[r1 + c];
            qh[kk][2] = *(const unsigned*)&Qhb[r0 + c + 8];
            qh[kk][3] = *(const unsigned*)&Qhb[r1 + c + 8];
            ql[kk][0] = *(const unsigned*)&Qlb[r0 + c];
            ql[kk][1] = *(const unsigned*)&Qlb[r1 + c];
            ql[kk][2] = *(const unsigned*)&Qlb[r0 + c + 8];
            ql[kk][3] = *(const unsigned*)&Qlb[r1 + c + 8];
        }
    }

    // tile loaders
    auto issue_K = [&](int kt, int stg) {
#pragma unroll
        for (int i = 0; i < 4; i++) {
            int chunk = t + i * 256;
            int arr = chunk >> 9;          // 0: hi, 1: lo
            int cid = chunk & 511;
            int row = cid >> 3, seg = cid & 7;
            unsigned dst = smb + (unsigned)(stg * STAGE + arr * 4608 + row * ALD) * 2 + seg * 16;
            const __nv_bfloat16* src =
                (arr ? Klb : Khb) + (size_t)(kt * 64 + row) * DK_ + seg * 8;
            CP_ASYNC16(dst, src);
        }
        CP_COMMIT();
    };
    float4 vreg[4];
    auto issue_V = [&](int kt) {
#pragma unroll
        for (int a = 0; a < 2; a++)
#pragma unroll
            for (int i = 0; i < 2; i++) {
                int id = t + i * 256;
                int row = id >> 3, seg = id & 7;
                vreg[a * 2 + i] = *(const float4*)&(
                    (a ? Vlb : Vhb)[(size_t)(kt * 64 + row) * DK_ + seg * 8]);
            }
    };
    auto store_V = [&](int stg) {
#pragma unroll
        for (int a = 0; a < 2; a++)
#pragma unroll
            for (int i = 0; i < 2; i++) {
                int id = t + i * 256;
                int row = id >> 3, seg = id & 7;
                const __nv_bfloat16* p = (const __nv_bfloat16*)&vreg[a * 2 + i];
                int base = stg * STAGE + (a ? 13824 : 9216);
#pragma unroll
                for (int j = 0; j < 8; j++) {
                    int jj = (j + seg) & 7;       // rotation: fewer bank conflicts
                    int d  = seg * 8 + jj;
                    sm[base + d * ALD + row] = p[jj];
                }
            }
    };

    float m0v = NEG, m1v = NEG, l0v = 0.f, l1v = 0.f;
    float o[8][4];
#pragma unroll
    for (int ni = 0; ni < 8; ni++)
#pragma unroll
        for (int j = 0; j < 4; j++) o[ni][j] = 0.f;

    const int ktmax = 2 * qt + 2;

    // prologue: stage 0 gets kt=0
    issue_K(0, 0);
    issue_V(0);
    store_V(0);

    for (int kt = 0; kt < ktmax; kt++) {
        const int s = kt & 1;
        CP_WAIT0();
        __syncthreads();

        const bool pf = (kt + 1 < ktmax);
        if (pf) {
            issue_K(kt + 1, s ^ 1);
            issue_V(kt + 1);
        }

        const __nv_bfloat16* sKh = sm + s * STAGE;
        const __nv_bfloat16* sKl = sKh + 4608;
        const __nv_bfloat16* sVh = sKh + 9216;
        const __nv_bfloat16* sVl = sKh + 13824;

        // ---- S = Q K^T ----
        float sc_[8][4];
#pragma unroll
        for (int ni = 0; ni < 8; ni++) {
#pragma unroll
            for (int j = 0; j < 4; j++) sc_[ni][j] = 0.f;
#pragma unroll
            for (int kk = 0; kk < 4; kk++) {
                int off = (ni * 8 + g) * ALD + kk * 16 + tg * 2;
                unsigned kh0 = *(const unsigned*)&sKh[off];
                unsigned kh1 = *(const unsigned*)&sKh[off + 8];
                unsigned kl0 = *(const unsigned*)&sKl[off];
                unsigned kl1 = *(const unsigned*)&sKl[off + 8];
                mma16816(sc_[ni], qh[kk], kh0, kh1);
                mma16816(sc_[ni], qh[kk], kl0, kl1);
                mma16816(sc_[ni], ql[kk], kh0, kh1);
            }
        }

        // ---- scale + causal mask ----
        const float scale = 0.125f;
        const int rA = qt * 128 + w * 16 + g;
        const int rB = rA + 8;
        if (kt * 64 + 63 > qt * 128 + w * 16) {
#pragma unroll
            for (int ni = 0; ni < 8; ni++) {
                int c0 = kt * 64 + ni * 8 + tg * 2;
                sc_[ni][0] = (c0     > rA) ? NEG : sc_[ni][0] * scale;
                sc_[ni][1] = (c0 + 1 > rA) ? NEG : sc_[ni][1] * scale;
                sc_[ni][2] = (c0     > rB) ? NEG : sc_[ni][2] * scale;
                sc_[ni][3] = (c0 + 1 > rB) ? NEG : sc_[ni][3] * scale;
            }
        } else {
#pragma unroll
            for (int ni = 0; ni < 8; ni++)
#pragma unroll
                for (int j = 0; j < 4; j++) sc_[ni][j] *= scale;
        }

        // ---- streaming softmax ----
        float mx0 = NEG, mx1 = NEG;
#pragma unroll
        for (int ni = 0; ni < 8; ni++) {
            mx0 = fmaxf(mx0, fmaxf(sc_[ni][0], sc_[ni][1]));
            mx1 = fmaxf(mx1, fmaxf(sc_[ni][2], sc_[ni][3]));
        }
        mx0 = fmaxf(mx0, __shfl_xor_sync(0xffffffffu, mx0, 1));
        mx0 = fmaxf(mx0, __shfl_xor_sync(0xffffffffu, mx0, 2));
        mx1 = fmaxf(mx1, __shfl_xor_sync(0xffffffffu, mx1, 1));
        mx1 = fmaxf(mx1, __shfl_xor_sync(0xffffffffu, mx1, 2));

        float nm0 = fmaxf(m0v, mx0), nm1 = fmaxf(m1v, mx1);
        float corr0 = __expf(m0v - nm0), corr1 = __expf(m1v - nm1);

        float sum0 = 0.f, sum1 = 0.f;
#pragma unroll
        for (int ni = 0; ni < 8; ni++) {
            sc_[ni][0] = __expf(sc_[ni][0] - nm0);
            sc_[ni][1] = __expf(sc_[ni][1] - nm0);
            sc_[ni][2] = __expf(sc_[ni][2] - nm1);
            sc_[ni][3] = __expf(sc_[ni][3] - nm1);
            sum0 += sc_[ni][0] + sc_[ni][1];
            sum1 += sc_[ni][2] + sc_[ni][3];
        }
        sum0 += __shfl_xor_sync(0xffffffffu, sum0, 1);
        sum0 += __shfl_xor_sync(0xffffffffu, sum0, 2);
        sum1 += __shfl_xor_sync(0xffffffffu, sum1, 1);
        sum1 += __shfl_xor_sync(0xffffffffu, sum1, 2);

        l0v = l0v * corr0 + sum0;
        l1v = l1v * corr1 + sum1;
        m0v = nm0; m1v = nm1;

#pragma unroll
        for (int ni = 0; ni < 8; ni++) {
            o[ni][0] *= corr0; o[ni][1] *= corr0;
            o[ni][2] *= corr1; o[ni][3] *= corr1;
        }

        if (pf) store_V(s ^ 1);

        // ---- O += P V ----
#pragma unroll
        for (int j = 0; j < 4; j++) {
            unsigned ah[4], al[4];
            {
                __nv_bfloat16 h0, l0, h1, l1;
                splitf(sc_[2 * j][0], h0, l0); splitf(sc_[2 * j][1], h1, l1);
                ah[0] = packh(h0, h1); al[0] = packh(l0, l1);
                splitf(sc_[2 * j][2], h0, l0); splitf(sc_[2 * j][3], h1, l1);
                ah[1] = packh(h0, h1); al[1] = packh(l0, l1);
                splitf(sc_[2 * j + 1][0], h0, l0); splitf(sc_[2 * j + 1][1], h1, l1);
                ah[2] = packh(h0, h1); al[2] = packh(l0, l1);
                splitf(sc_[2 * j + 1][2], h0, l0); splitf(sc_[2 * j + 1][3], h1, l1);
                ah[3] = packh(h0, h1); al[3] = packh(l0, l1);
            }
#pragma unroll
            for (int ni = 0; ni < 8; ni++) {
                int off = (ni * 8 + g) * ALD + j * 16 + tg * 2;
                unsigned vh0 = *(const unsigned*)&sVh[off];
                unsigned vh1 = *(const unsigned*)&sVh[off + 8];
                unsigned vl0 = *(const unsigned*)&sVl[off];
                unsigned vl1 = *(const unsigned*)&sVl[off + 8];
                mma16816(o[ni], ah, vh0, vh1);
                mma16816(o[ni], ah, vl0, vl1);
                mma16816(o[ni], al, vh0, vh1);
            }
        }
    }

    // ---- finalize ----
    float inv0 = 1.f / l0v, inv1 = 1.f / l1v;
    int bb = bh >> 4, hh = bh & 15;
    int q0 = qt * 128 + w * 16 + g;
#pragma unroll
    for (int ni = 0; ni < 8; ni++) {
        int d = ni * 8 + tg * 2;
        size_t i0 = ((size_t)(bb * S_ + q0)) * D_ + hh * 64 + d;
        size_t i1 = ((size_t)(bb * S_ + q0 + 8)) * D_ + hh * 64 + d;
        ctx[i0]     = o[ni][0] * inv0;
        ctx[i0 + 1] = o[ni][1] * inv0;
        ctx[i1]     = o[ni][2] * inv1;
        ctx[i1 + 1] = o[ni][3] * inv1;
    }
}

// ============================================================================
// Launch
// ============================================================================
extern "C" void kernel_launch(void* const* d_in, const int* in_sizes, int n_in,
                              void* d_out, int out_size)
{
    const float* q  = (const float*)d_in[0];
    const float* k  = (const float*)d_in[1];
    const float* v  = (const float*)d_in[2];
    const float* wq = (const float*)d_in[4];
    const float* bq = (const float*)d_in[5];
    const float* wk = (const float*)d_in[6];
    const float* bk = (const float*)d_in[7];
    const float* wv = (const float*)d_in[8];
    const float* bv = (const float*)d_in[9];
    const float* wo = (const float*)d_in[10];
    const float* bo = (const float*)d_in[11];
    float* out = (float*)d_out;

    __nv_bfloat16 *gh, *gl;
    float* gctx;
    cudaGetSymbolAddress((void**)&gh, g_h);
    cudaGetSymbolAddress((void**)&gl, g_l);
    cudaGetSymbolAddress((void**)&gctx, g_ctx);

    cudaFuncSetAttribute(attn_kernel,
                         cudaFuncAttributeMaxDynamicSharedMemorySize, ATTN_SMEM);

    // fused QKV projections
    gemm_kernel<0><<<dim3(8, 32, 3), 256>>>(q, k, v,
                                            wq, bq, wk, bk, wv, bv,
                                            gh, gl, nullptr);

    attn_kernel<<<dim3(S_ / 128, B_ * H_), 256, ATTN_SMEM>>>(gh, gl, gctx);

    // output projection
    gemm_kernel<1><<<dim3(8, 32, 1), 256>>>(gctx, nullptr, nullptr,
                                            wo, bo, nullptr, nullptr, nullptr, nullptr,
                                            nullptr, nullptr, out);
}

// round 5
// speedup vs baseline: 1.3338x; 1.0157x over previous
#include <cuda_runtime.h>
#include <cuda_bf16.h>
#include <cstdint>

#define DINLINE __device__ __forceinline__

constexpr int B_  = 2;
constexpr int S_  = 2048;
constexpr int D_  = 1024;
constexpr int H_  = 16;
constexpr int DK_ = 64;

constexpr size_t NQKV = (size_t)B_ * H_ * S_ * DK_;   // 4M elems
constexpr size_t XSZ  = (size_t)4096 * 1024;          // 4M
constexpr size_t WSZ  = (size_t)1024 * 1024;          // 1M

// ---------------- global scratch ----------------
__device__ __nv_bfloat16 g_xh[3 * XSZ], g_xl[3 * XSZ];     // q,k,v inputs split
__device__ __nv_bfloat16 g_wh[4 * WSZ], g_wl[4 * WSZ];     // wq,wk,wv,wo split
__device__ __nv_bfloat16 g_h[3 * NQKV], g_l[3 * NQKV];     // Q,K,V proj [B,H,S,DK]
__device__ __nv_bfloat16 g_ch[XSZ], g_cl[XSZ];             // attn context split

// ---------------- helpers ----------------
DINLINE unsigned packh(__nv_bfloat16 a, __nv_bfloat16 b) {
    __nv_bfloat162 v; v.x = a; v.y = b;
    return *reinterpret_cast<unsigned*>(&v);
}
DINLINE void splitf(float x, __nv_bfloat16& h, __nv_bfloat16& l) {
    h = __float2bfloat16(x);
    l = __float2bfloat16(x - __bfloat162float(h));
}
DINLINE void mma16816(float* c, const unsigned* a, unsigned b0, unsigned b1) {
    asm volatile(
        "mma.sync.aligned.m16n8k16.row.col.f32.bf16.bf16.f32 "
        "{%0,%1,%2,%3},{%4,%5,%6,%7},{%8,%9},{%0,%1,%2,%3};\n"
        : "+f"(c[0]), "+f"(c[1]), "+f"(c[2]), "+f"(c[3])
        : "r"(a[0]), "r"(a[1]), "r"(a[2]), "r"(a[3]), "r"(b0), "r"(b1));
}
DINLINE unsigned smem_u32(const void* p) {
    unsigned a;
    asm("{.reg .u64 t; cvta.to.shared.u64 t, %1; cvt.u32.u64 %0, t;}" : "=r"(a) : "l"(p));
    return a;
}
DINLINE void ldsm_x4(unsigned* r, unsigned addr) {
    asm volatile("ldmatrix.sync.aligned.m8n8.x4.shared.b16 {%0,%1,%2,%3}, [%4];"
                 : "=r"(r[0]), "=r"(r[1]), "=r"(r[2]), "=r"(r[3]) : "r"(addr));
}
DINLINE void ldsm_x4t(unsigned* r, unsigned addr) {
    asm volatile("ldmatrix.sync.aligned.m8n8.x4.trans.shared.b16 {%0,%1,%2,%3}, [%4];"
                 : "=r"(r[0]), "=r"(r[1]), "=r"(r[2]), "=r"(r[3]) : "r"(addr));
}

#define CP_ASYNC16(dst, src) \
    asm volatile("cp.async.cg.shared.global [%0], [%1], 16;\n" :: "r"(dst), "l"(src))
#define CP_COMMIT()  asm volatile("cp.async.commit_group;\n")
#define CP_WAIT0()   asm volatile("cp.async.wait_group 0;\n")
#define CP_WAIT1()   asm volatile("cp.async.wait_group 1;\n")
#define CP_WAIT2()   asm volatile("cp.async.wait_group 2;\n")

// ============================================================================
// convert: f32 inputs/weights -> bf16 hi/lo global buffers
// ============================================================================
__global__ void __launch_bounds__(256) convert_kernel(
    const float* __restrict__ q, const float* __restrict__ k, const float* __restrict__ v,
    const float* __restrict__ wq, const float* __restrict__ wk,
    const float* __restrict__ wv, const float* __restrict__ wo)
{
    size_t i = ((size_t)blockIdx.x * 256 + threadIdx.x) * 4;
    const float* src;
    __nv_bfloat16 *dh, *dl;
    size_t off;
    if (i < (size_t)3 * XSZ) {
        int z = (int)(i / XSZ);
        off = i - (size_t)z * XSZ;
        src = (z == 0) ? q : (z == 1) ? k : v;
        dh = g_xh + (size_t)z * XSZ; dl = g_xl + (size_t)z * XSZ;
    } else {
        size_t j = i - (size_t)3 * XSZ;
        int z = (int)(j / WSZ);
        off = j - (size_t)z * WSZ;
        src = (z == 0) ? wq : (z == 1) ? wk : (z == 2) ? wv : wo;
        dh = g_wh + (size_t)z * WSZ; dl = g_wl + (size_t)z * WSZ;
    }
    float4 val = *(const float4*)(src + off);
    __nv_bfloat16 h0, l0, h1, l1, h2, l2, h3, l3;
    splitf(val.x, h0, l0); splitf(val.y, h1, l1);
    splitf(val.z, h2, l2); splitf(val.w, h3, l3);
    uint2 uh = { packh(h0, h1), packh(h2, h3) };
    uint2 ul = { packh(l0, l1), packh(l2, l3) };
    *(uint2*)(dh + off) = uh;
    *(uint2*)(dl + off) = ul;
}

// ============================================================================
// GEMM: Y[4096,1024] = X @ W^T + b, pre-split bf16 hi/lo, 3-term.
// Tile 128x128, 256 threads (8 warps, warptile 32x64), BK=32,
// 3-stage cp.async pipeline, ldmatrix fragment loads.
// MODE 0: z selects (X,W,b); hi/lo bf16 out [B,H,S,DK].  MODE 1: f32 out.
// ============================================================================
constexpr int GLD      = 40;                   // smem row stride (elems), 80B
constexpr int G_ARR    = 128 * GLD;            // 5120 elems per array
constexpr int G_STAGE  = 4 * G_ARR;            // Ah,Al,Bh,Bl per stage
constexpr int GEMM_SMEM = 3 * G_STAGE * 2;     // 122880 bytes

template<int MODE>
__global__ void __launch_bounds__(256) gemm_kernel(
    const __nv_bfloat16* __restrict__ Ahg, const __nv_bfloat16* __restrict__ Alg,
    const __nv_bfloat16* __restrict__ Whg, const __nv_bfloat16* __restrict__ Wlg,
    const float* __restrict__ b0p, const float* __restrict__ b1p, const float* __restrict__ b2p,
    __nv_bfloat16* __restrict__ Yh, __nv_bfloat16* __restrict__ Yl,
    float* __restrict__ Yf)
{
    extern __shared__ __nv_bfloat16 gsm[];
    const unsigned smb = smem_u32(gsm);

    const int z = (MODE == 0) ? blockIdx.z : 0;
    const __nv_bfloat16* Ah = Ahg + (size_t)z * XSZ;
    const __nv_bfloat16* Al = Alg + (size_t)z * XSZ;
    const __nv_bfloat16* Bh = Whg + (size_t)z * WSZ;
    const __nv_bfloat16* Bl = Wlg + (size_t)z * WSZ;
    const float* bias = (z == 0) ? b0p : (z == 1) ? b1p : b2p;

    const int t    = threadIdx.x;
    const int w    = t >> 5;
    const int lane = t & 31;
    const int g    = lane >> 2;
    const int tg   = lane & 3;
    const int lm   = lane >> 3;   // ldmatrix matrix id
    const int lr   = lane & 7;    // ldmatrix row-in-matrix
    const int wm   = w >> 1;      // 0..3
    const int wn   = w & 1;       // 0..1
    const int m0   = blockIdx.y * 128;
    const int n0   = blockIdx.x * 128;

    // per-lane ldmatrix element-offset bases
    int abase[2], bbase[4];
#pragma unroll
    for (int mi = 0; mi < 2; mi++)
        abase[mi] = (wm * 32 + mi * 16 + ((lm & 1) << 3) + lr) * GLD + ((lm >> 1) << 3);
#pragma unroll
    for (int p = 0; p < 4; p++)
        bbase[p] = (wn * 64 + p * 16 + ((lm >> 1) << 3) + lr) * GLD + ((lm & 1) << 3);

    float acc[2][8][4];
#pragma unroll
    for (int mi = 0; mi < 2; mi++)
#pragma unroll
        for (int ni = 0; ni < 8; ni++)
#pragma unroll
            for (int j = 0; j < 4; j++) acc[mi][ni][j] = 0.f;

    auto issue_stage = [&](int kt, int stg) {
        unsigned base = (unsigned)(stg * G_STAGE);
#pragma unroll
        for (int i = 0; i < 8; i++) {
            int id = t + i * 256;
            int a_ = id >> 9;                 // array 0..3
            int cid = id & 511;
            int row = cid >> 2, seg = cid & 3;
            const __nv_bfloat16* gp =
                (a_ == 0) ? Ah : (a_ == 1) ? Al : (a_ == 2) ? Bh : Bl;
            const int r0 = (a_ < 2) ? m0 : n0;
            unsigned dst = smb + (base + a_ * G_ARR + row * GLD + seg * 8) * 2;
            CP_ASYNC16(dst, gp + (size_t)(r0 + row) * 1024 + (size_t)kt * 32 + seg * 8);
        }
        CP_COMMIT();
    };

    issue_stage(0, 0);
    issue_stage(1, 1);
    issue_stage(2, 2);

    for (int kt = 0; kt < 32; kt++) {
        if (kt < 30) CP_WAIT2();
        else if (kt == 30) CP_WAIT1();
        else CP_WAIT0();
        __syncthreads();

        const unsigned sb = (unsigned)((kt % 3) * G_STAGE);
#pragma unroll
        for (int kk = 0; kk < 32; kk += 16) {
            unsigned ah[2][4], al[2][4], bh[4][4], bl[4][4];
#pragma unroll
            for (int mi = 0; mi < 2; mi++) {
                ldsm_x4(ah[mi], smb + (sb + abase[mi] + kk) * 2);
                ldsm_x4(al[mi], smb + (sb + G_ARR + abase[mi] + kk) * 2);
            }
#pragma unroll
            for (int p = 0; p < 4; p++) {
                ldsm_x4(bh[p], smb + (sb + 2 * G_ARR + bbase[p] + kk) * 2);
                ldsm_x4(bl[p], smb + (sb + 3 * G_ARR + bbase[p] + kk) * 2);
            }
#pragma unroll
            for (int ni = 0; ni < 8; ni++) {
                const int p = ni >> 1, ix = (ni & 1) * 2;
                unsigned b0h = bh[p][ix], b1h = bh[p][ix + 1];
                unsigned b0l = bl[p][ix], b1l = bl[p][ix + 1];
#pragma unroll
                for (int mi = 0; mi < 2; mi++) {
                    mma16816(acc[mi][ni], ah[mi], b0h, b1h);
                    mma16816(acc[mi][ni], ah[mi], b0l, b1l);
                    mma16816(acc[mi][ni], al[mi], b0h, b1h);
                }
            }
        }
        __syncthreads();
        if (kt + 3 < 32) issue_stage(kt + 3, kt % 3);
    }

    // ---- epilogue ----
    const size_t zoff = (size_t)z * NQKV;
#pragma unroll
    for (int mi = 0; mi < 2; mi++) {
#pragma unroll
        for (int ni = 0; ni < 8; ni++) {
            int r = m0 + wm * 32 + mi * 16 + g;
            int c = n0 + wn * 64 + ni * 8 + tg * 2;
            float b0 = bias[c], b1 = bias[c + 1];
            float v00 = acc[mi][ni][0] + b0;
            float v01 = acc[mi][ni][1] + b1;
            float v10 = acc[mi][ni][2] + b0;
            float v11 = acc[mi][ni][3] + b1;
            if (MODE == 0) {
                int bb = r >> 11, ss = r & 2047;
                int hh = c >> 6, d = c & 63;
                size_t i0 = zoff + ((size_t)(bb * H_ + hh) * S_ + ss) * DK_ + d;
                size_t i1 = zoff + ((size_t)(bb * H_ + hh) * S_ + (ss + 8)) * DK_ + d;
                __nv_bfloat16 h0, l0, h1, l1;
                splitf(v00, h0, l0); splitf(v01, h1, l1);
                *(unsigned*)&Yh[i0] = packh(h0, h1);
                *(unsigned*)&Yl[i0] = packh(l0, l1);
                splitf(v10, h0, l0); splitf(v11, h1, l1);
                *(unsigned*)&Yh[i1] = packh(h0, h1);
                *(unsigned*)&Yl[i1] = packh(l0, l1);
            } else {
                Yf[(size_t)r * 1024 + c]           = v00;
                Yf[(size_t)r * 1024 + c + 1]       = v01;
                Yf[(size_t)(r + 8) * 1024 + c]     = v10;
                Yf[(size_t)(r + 8) * 1024 + c + 1] = v11;
            }
        }
    }
}

// ============================================================================
// Flash attention (causal), DK=64, Q-tile 128 (8 warps x 16 rows), KV-tile 64.
// K AND V stream row-major [kv][dk] via cp.async double buffer.
// K frags: ldmatrix.x4;  V frags: ldmatrix.x4.trans (free transpose).
// ============================================================================
constexpr int ALD = 72;
constexpr int A_ARR = 64 * ALD;         // 4608 elems per array
constexpr int STAGE = 4 * A_ARR;        // Kh,Kl,Vh,Vl
constexpr int ATTN_SMEM = 2 * STAGE * 2;

__global__ void __launch_bounds__(256, 1) attn_kernel(
    const __nv_bfloat16* __restrict__ Gh, const __nv_bfloat16* __restrict__ Gl,
    __nv_bfloat16* __restrict__ Ch, __nv_bfloat16* __restrict__ Cl)
{
    extern __shared__ __nv_bfloat16 sm[];

    const int qt   = blockIdx.x;
    const int bh   = blockIdx.y;
    const int t    = threadIdx.x;
    const int w    = t >> 5;
    const int lane = t & 31;
    const int g    = lane >> 2;
    const int tg   = lane & 3;
    const int lm   = lane >> 3;
    const int lr   = lane & 7;

    const size_t hb = (size_t)bh * S_ * DK_;
    const __nv_bfloat16* Qhb = Gh + hb;
    const __nv_bfloat16* Qlb = Gl + hb;
    const __nv_bfloat16* Khb = Gh + NQKV + hb;
    const __nv_bfloat16* Klb = Gl + NQKV + hb;
    const __nv_bfloat16* Vhb = Gh + 2 * NQKV + hb;
    const __nv_bfloat16* Vlb = Gl + 2 * NQKV + hb;

    const unsigned smb = smem_u32(sm);
    const float NEG = -1e30f;

    // ldmatrix per-lane bases (element offsets)
    const int kbase = lr * ALD + (lm << 3);                        // K (non-trans)
    const int vbase = (((lm & 1) << 3) + lr) * ALD + ((lm >> 1) << 3);  // V (trans)

    // ---- Q fragments straight from global ----
    unsigned qh[4][4], ql[4][4];
    {
        size_t r0 = (size_t)(qt * 128 + w * 16 + g) * DK_;
        size_t r1 = r0 + 8 * DK_;
#pragma unroll
        for (int kk = 0; kk < 4; kk++) {
            int c = kk * 16 + tg * 2;
            qh[kk][0] = *(const unsigned*)&Qhb[r0 + c];
            qh[kk][1] = *(const unsigned*)&Qhb[r1 + c];
            qh[kk][2] = *(const unsigned*)&Qhb[r0 + c + 8];
            qh[kk][3] = *(const unsigned*)&Qhb[r1 + c + 8];
            ql[kk][0] = *(const unsigned*)&Qlb[r0 + c];
            ql[kk][1] = *(const unsigned*)&Qlb[r1 + c];
            ql[kk][2] = *(const unsigned*)&Qlb[r0 + c + 8];
            ql[kk][3] = *(const unsigned*)&Qlb[r1 + c + 8];
        }
    }

    // stream K+V tiles: 4 arrays x 64 rows x 8 chunks = 2048 chunks, 8/thread
    auto issue_tile = [&](int kt, int stg) {
#pragma unroll
        for (int i = 0; i < 8; i++) {
            int id = t + i * 256;
            int a_ = id >> 9;
            int cid = id & 511;
            int row = cid >> 3, seg = cid & 7;
            const __nv_bfloat16* gp =
                (a_ == 0) ? Khb : (a_ == 1) ? Klb : (a_ == 2) ? Vhb : Vlb;
            unsigned dst = smb + (unsigned)(stg * STAGE + a_ * A_ARR + row * ALD + seg * 8) * 2;
            CP_ASYNC16(dst, gp + (size_t)(kt * 64 + row) * DK_ + seg * 8);
        }
        CP_COMMIT();
    };

    float m0v = NEG, m1v = NEG, l0v = 0.f, l1v = 0.f;
    float o[8][4];
#pragma unroll
    for (int ni = 0; ni < 8; ni++)
#pragma unroll
        for (int j = 0; j < 4; j++) o[ni][j] = 0.f;

    const int ktmax = 2 * qt + 2;
    issue_tile(0, 0);

    for (int kt = 0; kt < ktmax; kt++) {
        const int s = kt & 1;
        CP_WAIT0();
        __syncthreads();

        if (kt + 1 < ktmax) issue_tile(kt + 1, s ^ 1);

        const unsigned sb = (unsigned)(s * STAGE);

        // ---- S = Q K^T ----
        float sc_[8][4];
#pragma unroll
        for (int ni = 0; ni < 8; ni++) {
#pragma unroll
            for (int j = 0; j < 4; j++) sc_[ni][j] = 0.f;
            unsigned kh[2][4], kl[2][4];
#pragma unroll
            for (int q = 0; q < 2; q++) {
                unsigned off = sb + ni * 8 * ALD + q * 32 + kbase;
                ldsm_x4(kh[q], smb + off * 2);
                ldsm_x4(kl[q], smb + (off + A_ARR) * 2);
            }
#pragma unroll
            for (int kk = 0; kk < 4; kk++) {
                const int q = kk >> 1, ix = (kk & 1) * 2;
                unsigned b0h = kh[q][ix], b1h = kh[q][ix + 1];
                unsigned b0l = kl[q][ix], b1l = kl[q][ix + 1];
                mma16816(sc_[ni], qh[kk], b0h, b1h);
                mma16816(sc_[ni], qh[kk], b0l, b1l);
                mma16816(sc_[ni], ql[kk], b0h, b1h);
            }
        }

        // ---- scale + causal mask ----
        const float scale = 0.125f;
        const int rA = qt * 128 + w * 16 + g;
        const int rB = rA + 8;
        if (kt * 64 + 63 > qt * 128 + w * 16) {
#pragma unroll
            for (int ni = 0; ni < 8; ni++) {
                int c0 = kt * 64 + ni * 8 + tg * 2;
                sc_[ni][0] = (c0     > rA) ? NEG : sc_[ni][0] * scale;
                sc_[ni][1] = (c0 + 1 > rA) ? NEG : sc_[ni][1] * scale;
                sc_[ni][2] = (c0     > rB) ? NEG : sc_[ni][2] * scale;
                sc_[ni][3] = (c0 + 1 > rB) ? NEG : sc_[ni][3] * scale;
            }
        } else {
#pragma unroll
            for (int ni = 0; ni < 8; ni++)
#pragma unroll
                for (int j = 0; j < 4; j++) sc_[ni][j] *= scale;
        }

        // ---- streaming softmax ----
        float mx0 = NEG, mx1 = NEG;
#pragma unroll
        for (int ni = 0; ni < 8; ni++) {
            mx0 = fmaxf(mx0, fmaxf(sc_[ni][0], sc_[ni][1]));
            mx1 = fmaxf(mx1, fmaxf(sc_[ni][2], sc_[ni][3]));
        }
        mx0 = fmaxf(mx0, __shfl_xor_sync(0xffffffffu, mx0, 1));
        mx0 = fmaxf(mx0, __shfl_xor_sync(0xffffffffu, mx0, 2));
        mx1 = fmaxf(mx1, __shfl_xor_sync(0xffffffffu, mx1, 1));
        mx1 = fmaxf(mx1, __shfl_xor_sync(0xffffffffu, mx1, 2));

        float nm0 = fmaxf(m0v, mx0), nm1 = fmaxf(m1v, mx1);
        float corr0 = __expf(m0v - nm0), corr1 = __expf(m1v - nm1);

        float sum0 = 0.f, sum1 = 0.f;
#pragma unroll
        for (int ni = 0; ni < 8; ni++) {
            sc_[ni][0] = __expf(sc_[ni][0] - nm0);
            sc_[ni][1] = __expf(sc_[ni][1] - nm0);
            sc_[ni][2] = __expf(sc_[ni][2] - nm1);
            sc_[ni][3] = __expf(sc_[ni][3] - nm1);
            sum0 += sc_[ni][0] + sc_[ni][1];
            sum1 += sc_[ni][2] + sc_[ni][3];
        }
        sum0 += __shfl_xor_sync(0xffffffffu, sum0, 1);
        sum0 += __shfl_xor_sync(0xffffffffu, sum0, 2);
        sum1 += __shfl_xor_sync(0xffffffffu, sum1, 1);
        sum1 += __shfl_xor_sync(0xffffffffu, sum1, 2);

        l0v = l0v * corr0 + sum0;
        l1v = l1v * corr1 + sum1;
        m0v = nm0; m1v = nm1;

#pragma unroll
        for (int ni = 0; ni < 8; ni++) {
            o[ni][0] *= corr0; o[ni][1] *= corr0;
            o[ni][2] *= corr1; o[ni][3] *= corr1;
        }

        // ---- O += P V  (V frags via ldmatrix.trans) ----
#pragma unroll
        for (int j = 0; j < 4; j++) {
            unsigned ah[4], al[4];
            {
                __nv_bfloat16 h0, l0, h1, l1;
                splitf(sc_[2 * j][0], h0, l0); splitf(sc_[2 * j][1], h1, l1);
                ah[0] = packh(h0, h1); al[0] = packh(l0, l1);
                splitf(sc_[2 * j][2], h0, l0); splitf(sc_[2 * j][3], h1, l1);
                ah[1] = packh(h0, h1); al[1] = packh(l0, l1);
                splitf(sc_[2 * j + 1][0], h0, l0); splitf(sc_[2 * j + 1][1], h1, l1);
                ah[2] = packh(h0, h1); al[2] = packh(l0, l1);
                splitf(sc_[2 * j + 1][2], h0, l0); splitf(sc_[2 * j + 1][3], h1, l1);
                ah[3] = packh(h0, h1); al[3] = packh(l0, l1);
            }
            unsigned vh[4][4], vl[4][4];
#pragma unroll
            for (int p = 0; p < 4; p++) {
                unsigned off = sb + 2 * A_ARR + j * 16 * ALD + p * 16 + vbase;
                ldsm_x4t(vh[p], smb + off * 2);
                ldsm_x4t(vl[p], smb + (off + A_ARR) * 2);
            }
#pragma unroll
            for (int ni = 0; ni < 8; ni++) {
                const int p = ni >> 1, ix = (ni & 1) * 2;
                unsigned b0h = vh[p][ix], b1h = vh[p][ix + 1];
                unsigned b0l = vl[p][ix], b1l = vl[p][ix + 1];
                mma16816(o[ni], ah, b0h, b1h);
                mma16816(o[ni], ah, b0l, b1l);
                mma16816(o[ni], al, b0h, b1h);
            }
        }
    }

    // ---- finalize -> hi/lo bf16 context ----
    float inv0 = 1.f / l0v, inv1 = 1.f / l1v;
    int bb = bh >> 4, hh = bh & 15;
    int q0 = qt * 128 + w * 16 + g;
#pragma unroll
    for (int ni = 0; ni < 8; ni++) {
        int d = ni * 8 + tg * 2;
        size_t i0 = ((size_t)(bb * S_ + q0)) * D_ + hh * 64 + d;
        size_t i1 = ((size_t)(bb * S_ + q0 + 8)) * D_ + hh * 64 + d;
        __nv_bfloat16 h0, l0, h1, l1;
        splitf(o[ni][0] * inv0, h0, l0); splitf(o[ni][1] * inv0, h1, l1);
        *(unsigned*)&Ch[i0] = packh(h0, h1);
        *(unsigned*)&Cl[i0] = packh(l0, l1);
        splitf(o[ni][2] * inv1, h0, l0); splitf(o[ni][3] * inv1, h1, l1);
        *(unsigned*)&Ch[i1] = packh(h0, h1);
        *(unsigned*)&Cl[i1] = packh(l0, l1);
    }
}

// ============================================================================
// Launch
// ============================================================================
extern "C" void kernel_launch(void* const* d_in, const int* in_sizes, int n_in,
                              void* d_out, int out_size)
{
    const float* q  = (const float*)d_in[0];
    const float* k  = (const float*)d_in[1];
    const float* v  = (const float*)d_in[2];
    const float* wq = (const float*)d_in[4];
    const float* bq = (const float*)d_in[5];
    const float* wk = (const float*)d_in[6];
    const float* bk = (const float*)d_in[7];
    const float* wv = (const float*)d_in[8];
    const float* bv = (const float*)d_in[9];
    const float* wo = (const float*)d_in[10];
    const float* bo = (const float*)d_in[11];
    float* out = (float*)d_out;

    __nv_bfloat16 *gxh, *gxl, *gwh, *gwl, *gh, *gl, *gch, *gcl;
    cudaGetSymbolAddress((void**)&gxh, g_xh);
    cudaGetSymbolAddress((void**)&gxl, g_xl);
    cudaGetSymbolAddress((void**)&gwh, g_wh);
    cudaGetSymbolAddress((void**)&gwl, g_wl);
    cudaGetSymbolAddress((void**)&gh,  g_h);
    cudaGetSymbolAddress((void**)&gl,  g_l);
    cudaGetSymbolAddress((void**)&gch, g_ch);
    cudaGetSymbolAddress((void**)&gcl, g_cl);

    cudaFuncSetAttribute(gemm_kernel<0>,
                         cudaFuncAttributeMaxDynamicSharedMemorySize, GEMM_SMEM);
    cudaFuncSetAttribute(gemm_kernel<1>,
                         cudaFuncAttributeMaxDynamicSharedMemorySize, GEMM_SMEM);
    cudaFuncSetAttribute(attn_kernel,
                         cudaFuncAttributeMaxDynamicSharedMemorySize, ATTN_SMEM);

    // 1) split inputs + weights to bf16 hi/lo
    convert_kernel<<<16384, 256>>>(q, k, v, wq, wk, wv, wo);

    // 2) QKV projections
    gemm_kernel<0><<<dim3(8, 32, 3), 256, GEMM_SMEM>>>(
        gxh, gxl, gwh, gwl, bq, bk, bv, gh, gl, nullptr);

    // 3) attention
    attn_kernel<<<dim3(S_ / 128, B_ * H_), 256, ATTN_SMEM>>>(gh, gl, gch, gcl);

    // 4) output projection
    gemm_kernel<1><<<dim3(8, 32, 1), 256, GEMM_SMEM>>>(
        gch, gcl, gwh + 3 * WSZ, gwl + 3 * WSZ, bo, bo, bo, nullptr, nullptr, out);
}

// round 6
// speedup vs baseline: 1.5609x; 1.1702x over previous
#include <cuda_runtime.h>
#include <cuda_bf16.h>
#include <cstdint>

#define DINLINE __device__ __forceinline__

constexpr int B_  = 2;
constexpr int S_  = 2048;
constexpr int D_  = 1024;
constexpr int H_  = 16;
constexpr int DK_ = 64;

constexpr size_t NQKV = (size_t)B_ * H_ * S_ * DK_;   // 4M elems
constexpr size_t XSZ  = (size_t)4096 * 1024;          // 4M
constexpr size_t WSZ  = (size_t)1024 * 1024;          // 1M

// ---------------- global scratch ----------------
__device__ __nv_bfloat16 g_xh[3 * XSZ], g_xl[3 * XSZ];     // q,k,v inputs split
__device__ __nv_bfloat16 g_wh[4 * WSZ], g_wl[4 * WSZ];     // wq,wk,wv,wo split
__device__ __nv_bfloat16 g_h[3 * NQKV], g_l[3 * NQKV];     // Q,K,V proj [B,H,S,DK]
__device__ __nv_bfloat16 g_ch[XSZ], g_cl[XSZ];             // attn context split

// ---------------- helpers ----------------
DINLINE unsigned packh(__nv_bfloat16 a, __nv_bfloat16 b) {
    __nv_bfloat162 v; v.x = a; v.y = b;
    return *reinterpret_cast<unsigned*>(&v);
}
DINLINE void splitf(float x, __nv_bfloat16& h, __nv_bfloat16& l) {
    h = __float2bfloat16(x);
    l = __float2bfloat16(x - __bfloat162float(h));
}
DINLINE void mma16816(float* c, const unsigned* a, unsigned b0, unsigned b1) {
    asm volatile(
        "mma.sync.aligned.m16n8k16.row.col.f32.bf16.bf16.f32 "
        "{%0,%1,%2,%3},{%4,%5,%6,%7},{%8,%9},{%0,%1,%2,%3};\n"
        : "+f"(c[0]), "+f"(c[1]), "+f"(c[2]), "+f"(c[3])
        : "r"(a[0]), "r"(a[1]), "r"(a[2]), "r"(a[3]), "r"(b0), "r"(b1));
}
DINLINE unsigned smem_u32(const void* p) {
    unsigned a;
    asm("{.reg .u64 t; cvta.to.shared.u64 t, %1; cvt.u32.u64 %0, t;}" : "=r"(a) : "l"(p));
    return a;
}
DINLINE void ldsm_x4(unsigned* r, unsigned addr) {
    asm volatile("ldmatrix.sync.aligned.m8n8.x4.shared.b16 {%0,%1,%2,%3}, [%4];"
                 : "=r"(r[0]), "=r"(r[1]), "=r"(r[2]), "=r"(r[3]) : "r"(addr));
}
DINLINE void ldsm_x4t(unsigned* r, unsigned addr) {
    asm volatile("ldmatrix.sync.aligned.m8n8.x4.trans.shared.b16 {%0,%1,%2,%3}, [%4];"
                 : "=r"(r[0]), "=r"(r[1]), "=r"(r[2]), "=r"(r[3]) : "r"(addr));
}

#define CP_ASYNC16(dst, src) \
    asm volatile("cp.async.cg.shared.global [%0], [%1], 16;\n" :: "r"(dst), "l"(src))
#define CP_COMMIT()  asm volatile("cp.async.commit_group;\n")
#define CP_WAIT0()   asm volatile("cp.async.wait_group 0;\n")
#define CP_WAIT1()   asm volatile("cp.async.wait_group 1;\n")

// ============================================================================
// convert: f32 inputs/weights -> bf16 hi/lo global buffers
// ============================================================================
__global__ void __launch_bounds__(256) convert_kernel(
    const float* __restrict__ q, const float* __restrict__ k, const float* __restrict__ v,
    const float* __restrict__ wq, const float* __restrict__ wk,
    const float* __restrict__ wv, const float* __restrict__ wo)
{
    size_t i = ((size_t)blockIdx.x * 256 + threadIdx.x) * 4;
    const float* src;
    __nv_bfloat16 *dh, *dl;
    size_t off;
    if (i < (size_t)3 * XSZ) {
        int z = (int)(i / XSZ);
        off = i - (size_t)z * XSZ;
        src = (z == 0) ? q : (z == 1) ? k : v;
        dh = g_xh + (size_t)z * XSZ; dl = g_xl + (size_t)z * XSZ;
    } else {
        size_t j = i - (size_t)3 * XSZ;
        int z = (int)(j / WSZ);
        off = j - (size_t)z * WSZ;
        src = (z == 0) ? wq : (z == 1) ? wk : (z == 2) ? wv : wo;
        dh = g_wh + (size_t)z * WSZ; dl = g_wl + (size_t)z * WSZ;
    }
    float4 val = *(const float4*)(src + off);
    __nv_bfloat16 h0, l0, h1, l1, h2, l2, h3, l3;
    splitf(val.x, h0, l0); splitf(val.y, h1, l1);
    splitf(val.z, h2, l2); splitf(val.w, h3, l3);
    uint2 uh = { packh(h0, h1), packh(h2, h3) };
    uint2 ul = { packh(l0, l1), packh(l2, l3) };
    *(uint2*)(dh + off) = uh;
    *(uint2*)(dl + off) = ul;
}

// ============================================================================
// GEMM: Y[4096,1024] = X @ W^T + b, pre-split bf16 hi/lo, 3-term.
// Tile 128x128, 256 threads (8 warps, warptile 32x64), BK=32,
// 2-stage cp.async pipeline, ldmatrix frag loads, 2 CTAs/SM.
// MODE 0: z selects (X,W,b); hi/lo bf16 out [B,H,S,DK].  MODE 1: f32 out.
// ============================================================================
constexpr int GLD      = 40;                   // smem row stride (elems), 80B
constexpr int G_ARR    = 128 * GLD;            // 5120 elems per array
constexpr int G_STAGE  = 4 * G_ARR;            // Ah,Al,Bh,Bl per stage
constexpr int GEMM_SMEM = 2 * G_STAGE * 2;     // 81920 bytes

template<int MODE>
__global__ void __launch_bounds__(256, 2) gemm_kernel(
    const __nv_bfloat16* __restrict__ Ahg, const __nv_bfloat16* __restrict__ Alg,
    const __nv_bfloat16* __restrict__ Whg, const __nv_bfloat16* __restrict__ Wlg,
    const float* __restrict__ b0p, const float* __restrict__ b1p, const float* __restrict__ b2p,
    __nv_bfloat16* __restrict__ Yh, __nv_bfloat16* __restrict__ Yl,
    float* __restrict__ Yf)
{
    extern __shared__ __nv_bfloat16 gsm[];
    const unsigned smb = smem_u32(gsm);

    const int z = (MODE == 0) ? blockIdx.z : 0;
    const __nv_bfloat16* Ah = Ahg + (size_t)z * XSZ;
    const __nv_bfloat16* Al = Alg + (size_t)z * XSZ;
    const __nv_bfloat16* Bh = Whg + (size_t)z * WSZ;
    const __nv_bfloat16* Bl = Wlg + (size_t)z * WSZ;
    const float* bias = (z == 0) ? b0p : (z == 1) ? b1p : b2p;

    const int t    = threadIdx.x;
    const int w    = t >> 5;
    const int lane = t & 31;
    const int g    = lane >> 2;
    const int tg   = lane & 3;
    const int lm   = lane >> 3;   // ldmatrix matrix id
    const int lr   = lane & 7;    // ldmatrix row-in-matrix
    const int wm   = w >> 1;      // 0..3
    const int wn   = w & 1;       // 0..1
    const int m0   = blockIdx.y * 128;
    const int n0   = blockIdx.x * 128;

    // per-lane ldmatrix element-offset bases
    int abase[2], bbase[4];
#pragma unroll
    for (int mi = 0; mi < 2; mi++)
        abase[mi] = (wm * 32 + mi * 16 + ((lm & 1) << 3) + lr) * GLD + ((lm >> 1) << 3);
#pragma unroll
    for (int p = 0; p < 4; p++)
        bbase[p] = (wn * 64 + p * 16 + ((lm >> 1) << 3) + lr) * GLD + ((lm & 1) << 3);

    float acc[2][8][4];
#pragma unroll
    for (int mi = 0; mi < 2; mi++)
#pragma unroll
        for (int ni = 0; ni < 8; ni++)
#pragma unroll
            for (int j = 0; j < 4; j++) acc[mi][ni][j] = 0.f;

    auto issue_stage = [&](int kt, int stg) {
        unsigned base = (unsigned)(stg * G_STAGE);
#pragma unroll
        for (int i = 0; i < 8; i++) {
            int id = t + i * 256;
            int a_ = id >> 9;                 // array 0..3
            int cid = id & 511;
            int row = cid >> 2, seg = cid & 3;
            const __nv_bfloat16* gp =
                (a_ == 0) ? Ah : (a_ == 1) ? Al : (a_ == 2) ? Bh : Bl;
            const int r0 = (a_ < 2) ? m0 : n0;
            unsigned dst = smb + (base + a_ * G_ARR + row * GLD + seg * 8) * 2;
            CP_ASYNC16(dst, gp + (size_t)(r0 + row) * 1024 + (size_t)kt * 32 + seg * 8);
        }
        CP_COMMIT();
    };

    issue_stage(0, 0);
    issue_stage(1, 1);

    for (int kt = 0; kt < 32; kt++) {
        const int s = kt & 1;
        if (kt < 31) CP_WAIT1(); else CP_WAIT0();
        __syncthreads();

        const unsigned sb = (unsigned)(s * G_STAGE);
#pragma unroll
        for (int kk = 0; kk < 32; kk += 16) {
            unsigned ah[2][4], al[2][4], bh[4][4], bl[4][4];
#pragma unroll
            for (int mi = 0; mi < 2; mi++) {
                ldsm_x4(ah[mi], smb + (sb + abase[mi] + kk) * 2);
                ldsm_x4(al[mi], smb + (sb + G_ARR + abase[mi] + kk) * 2);
            }
#pragma unroll
            for (int p = 0; p < 4; p++) {
                ldsm_x4(bh[p], smb + (sb + 2 * G_ARR + bbase[p] + kk) * 2);
                ldsm_x4(bl[p], smb + (sb + 3 * G_ARR + bbase[p] + kk) * 2);
            }
#pragma unroll
            for (int ni = 0; ni < 8; ni++) {
                const int p = ni >> 1, ix = (ni & 1) * 2;
                unsigned b0h = bh[p][ix], b1h = bh[p][ix + 1];
                unsigned b0l = bl[p][ix], b1l = bl[p][ix + 1];
#pragma unroll
                for (int mi = 0; mi < 2; mi++) {
                    mma16816(acc[mi][ni], ah[mi], b0h, b1h);
                    mma16816(acc[mi][ni], ah[mi], b0l, b1l);
                    mma16816(acc[mi][ni], al[mi], b0h, b1h);
                }
            }
        }
        __syncthreads();
        if (kt + 2 < 32) issue_stage(kt + 2, s);
    }

    // ---- epilogue ----
    const size_t zoff = (size_t)z * NQKV;
#pragma unroll
    for (int mi = 0; mi < 2; mi++) {
#pragma unroll
        for (int ni = 0; ni < 8; ni++) {
            int r = m0 + wm * 32 + mi * 16 + g;
            int c = n0 + wn * 64 + ni * 8 + tg * 2;
            float b0 = bias[c], b1 = bias[c + 1];
            float v00 = acc[mi][ni][0] + b0;
            float v01 = acc[mi][ni][1] + b1;
            float v10 = acc[mi][ni][2] + b0;
            float v11 = acc[mi][ni][3] + b1;
            if (MODE == 0) {
                int bb = r >> 11, ss = r & 2047;
                int hh = c >> 6, d = c & 63;
                size_t i0 = zoff + ((size_t)(bb * H_ + hh) * S_ + ss) * DK_ + d;
                size_t i1 = zoff + ((size_t)(bb * H_ + hh) * S_ + (ss + 8)) * DK_ + d;
                __nv_bfloat16 h0, l0, h1, l1;
                splitf(v00, h0, l0); splitf(v01, h1, l1);
                *(unsigned*)&Yh[i0] = packh(h0, h1);
                *(unsigned*)&Yl[i0] = packh(l0, l1);
                splitf(v10, h0, l0); splitf(v11, h1, l1);
                *(unsigned*)&Yh[i1] = packh(h0, h1);
                *(unsigned*)&Yl[i1] = packh(l0, l1);
            } else {
                Yf[(size_t)r * 1024 + c]           = v00;
                Yf[(size_t)r * 1024 + c + 1]       = v01;
                Yf[(size_t)(r + 8) * 1024 + c]     = v10;
                Yf[(size_t)(r + 8) * 1024 + c + 1] = v11;
            }
        }
    }
}

// ============================================================================
// Flash attention (causal), DK=64, Q-tile 128 (8 warps x 16 rows), KV-tile 64.
// K AND V stream row-major [kv][dk] via cp.async double buffer.
// K frags: ldmatrix.x4;  V frags: ldmatrix.x4.trans (free transpose).
// qt REVERSED so heavy CTAs launch first (wave load balance).
// ============================================================================
constexpr int ALD = 72;
constexpr int A_ARR = 64 * ALD;         // 4608 elems per array
constexpr int STAGE = 4 * A_ARR;        // Kh,Kl,Vh,Vl
constexpr int ATTN_SMEM = 2 * STAGE * 2;

__global__ void __launch_bounds__(256, 1) attn_kernel(
    const __nv_bfloat16* __restrict__ Gh, const __nv_bfloat16* __restrict__ Gl,
    __nv_bfloat16* __restrict__ Ch, __nv_bfloat16* __restrict__ Cl)
{
    extern __shared__ __nv_bfloat16 sm[];

    const int qt   = (int)gridDim.x - 1 - (int)blockIdx.x;  // heavy first
    const int bh   = blockIdx.y;
    const int t    = threadIdx.x;
    const int w    = t >> 5;
    const int lane = t & 31;
    const int g    = lane >> 2;
    const int tg   = lane & 3;
    const int lm   = lane >> 3;
    const int lr   = lane & 7;

    const size_t hb = (size_t)bh * S_ * DK_;
    const __nv_bfloat16* Qhb = Gh + hb;
    const __nv_bfloat16* Qlb = Gl + hb;
    const __nv_bfloat16* Khb = Gh + NQKV + hb;
    const __nv_bfloat16* Klb = Gl + NQKV + hb;
    const __nv_bfloat16* Vhb = Gh + 2 * NQKV + hb;
    const __nv_bfloat16* Vlb = Gl + 2 * NQKV + hb;

    const unsigned smb = smem_u32(sm);
    const float NEG = -1e30f;

    // ldmatrix per-lane bases (element offsets)
    const int kbase = lr * ALD + (lm << 3);                        // K (non-trans)
    const int vbase = (((lm & 1) << 3) + lr) * ALD + ((lm >> 1) << 3);  // V (trans)

    // ---- Q fragments straight from global ----
    unsigned qh[4][4], ql[4][4];
    {
        size_t r0 = (size_t)(qt * 128 + w * 16 + g) * DK_;
        size_t r1 = r0 + 8 * DK_;
#pragma unroll
        for (int kk = 0; kk < 4; kk++) {
            int c = kk * 16 + tg * 2;
            qh[kk][0] = *(const unsigned*)&Qhb[r0 + c];
            qh[kk][1] = *(const unsigned*)&Qhb[r1 + c];
            qh[kk][2] = *(const unsigned*)&Qhb[r0 + c + 8];
            qh[kk][3] = *(const unsigned*)&Qhb[r1 + c + 8];
            ql[kk][0] = *(const unsigned*)&Qlb[r0 + c];
            ql[kk][1] = *(const unsigned*)&Qlb[r1 + c];
            ql[kk][2] = *(const unsigned*)&Qlb[r0 + c + 8];
            ql[kk][3] = *(const unsigned*)&Qlb[r1 + c + 8];
        }
    }

    // stream K+V tiles: 4 arrays x 64 rows x 8 chunks = 2048 chunks, 8/thread
    auto issue_tile = [&](int kt, int stg) {
#pragma unroll
        for (int i = 0; i < 8; i++) {
            int id = t + i * 256;
            int a_ = id >> 9;
            int cid = id & 511;
            int row = cid >> 3, seg = cid & 7;
            const __nv_bfloat16* gp =
                (a_ == 0) ? Khb : (a_ == 1) ? Klb : (a_ == 2) ? Vhb : Vlb;
            unsigned dst = smb + (unsigned)(stg * STAGE + a_ * A_ARR + row * ALD + seg * 8) * 2;
            CP_ASYNC16(dst, gp + (size_t)(kt * 64 + row) * DK_ + seg * 8);
        }
        CP_COMMIT();
    };

    float m0v = NEG, m1v = NEG, l0v = 0.f, l1v = 0.f;
    float o[8][4];
#pragma unroll
    for (int ni = 0; ni < 8; ni++)
#pragma unroll
        for (int j = 0; j < 4; j++) o[ni][j] = 0.f;

    const int ktmax = 2 * qt + 2;
    issue_tile(0, 0);

    for (int kt = 0; kt < ktmax; kt++) {
        const int s = kt & 1;
        CP_WAIT0();
        __syncthreads();

        if (kt + 1 < ktmax) issue_tile(kt + 1, s ^ 1);

        const unsigned sb = (unsigned)(s * STAGE);

        // ---- S = Q K^T ----
        float sc_[8][4];
#pragma unroll
        for (int ni = 0; ni < 8; ni++) {
#pragma unroll
            for (int j = 0; j < 4; j++) sc_[ni][j] = 0.f;
            unsigned kh[2][4], kl[2][4];
#pragma unroll
            for (int q = 0; q < 2; q++) {
                unsigned off = sb + ni * 8 * ALD + q * 32 + kbase;
                ldsm_x4(kh[q], smb + off * 2);
                ldsm_x4(kl[q], smb + (off + A_ARR) * 2);
            }
#pragma unroll
            for (int kk = 0; kk < 4; kk++) {
                const int q = kk >> 1, ix = (kk & 1) * 2;
                unsigned b0h = kh[q][ix], b1h = kh[q][ix + 1];
                unsigned b0l = kl[q][ix], b1l = kl[q][ix + 1];
                mma16816(sc_[ni], qh[kk], b0h, b1h);
                mma16816(sc_[ni], qh[kk], b0l, b1l);
                mma16816(sc_[ni], ql[kk], b0h, b1h);
            }
        }

        // ---- scale + causal mask ----
        const float scale = 0.125f;
        const int rA = qt * 128 + w * 16 + g;
        const int rB = rA + 8;
        if (kt * 64 + 63 > qt * 128 + w * 16) {
#pragma unroll
            for (int ni = 0; ni < 8; ni++) {
                int c0 = kt * 64 + ni * 8 + tg * 2;
                sc_[ni][0] = (c0     > rA) ? NEG : sc_[ni][0] * scale;
                sc_[ni][1] = (c0 + 1 > rA) ? NEG : sc_[ni][1] * scale;
                sc_[ni][2] = (c0     > rB) ? NEG : sc_[ni][2] * scale;
                sc_[ni][3] = (c0 + 1 > rB) ? NEG : sc_[ni][3] * scale;
            }
        } else {
#pragma unroll
            for (int ni = 0; ni < 8; ni++)
#pragma unroll
                for (int j = 0; j < 4; j++) sc_[ni][j] *= scale;
        }

        // ---- streaming softmax ----
        float mx0 = NEG, mx1 = NEG;
#pragma unroll
        for (int ni = 0; ni < 8; ni++) {
            mx0 = fmaxf(mx0, fmaxf(sc_[ni][0], sc_[ni][1]));
            mx1 = fmaxf(mx1, fmaxf(sc_[ni][2], sc_[ni][3]));
        }
        mx0 = fmaxf(mx0, __shfl_xor_sync(0xffffffffu, mx0, 1));
        mx0 = fmaxf(mx0, __shfl_xor_sync(0xffffffffu, mx0, 2));
        mx1 = fmaxf(mx1, __shfl_xor_sync(0xffffffffu, mx1, 1));
        mx1 = fmaxf(mx1, __shfl_xor_sync(0xffffffffu, mx1, 2));

        float nm0 = fmaxf(m0v, mx0), nm1 = fmaxf(m1v, mx1);
        float corr0 = __expf(m0v - nm0), corr1 = __expf(m1v - nm1);

        float sum0 = 0.f, sum1 = 0.f;
#pragma unroll
        for (int ni = 0; ni < 8; ni++) {
            sc_[ni][0] = __expf(sc_[ni][0] - nm0);
            sc_[ni][1] = __expf(sc_[ni][1] - nm0);
            sc_[ni][2] = __expf(sc_[ni][2] - nm1);
            sc_[ni][3] = __expf(sc_[ni][3] - nm1);
            sum0 += sc_[ni][0] + sc_[ni][1];
            sum1 += sc_[ni][2] + sc_[ni][3];
        }
        sum0 += __shfl_xor_sync(0xffffffffu, sum0, 1);
        sum0 += __shfl_xor_sync(0xffffffffu, sum0, 2);
        sum1 += __shfl_xor_sync(0xffffffffu, sum1, 1);
        sum1 += __shfl_xor_sync(0xffffffffu, sum1, 2);

        l0v = l0v * corr0 + sum0;
        l1v = l1v * corr1 + sum1;
        m0v = nm0; m1v = nm1;

#pragma unroll
        for (int ni = 0; ni < 8; ni++) {
            o[ni][0] *= corr0; o[ni][1] *= corr0;
            o[ni][2] *= corr1; o[ni][3] *= corr1;
        }

        // ---- O += P V  (V frags via ldmatrix.trans) ----
#pragma unroll
        for (int j = 0; j < 4; j++) {
            unsigned ah[4], al[4];
            {
                __nv_bfloat16 h0, l0, h1, l1;
                splitf(sc_[2 * j][0], h0, l0); splitf(sc_[2 * j][1], h1, l1);
                ah[0] = packh(h0, h1); al[0] = packh(l0, l1);
                splitf(sc_[2 * j][2], h0, l0); splitf(sc_[2 * j][3], h1, l1);
                ah[1] = packh(h0, h1); al[1] = packh(l0, l1);
                splitf(sc_[2 * j + 1][0], h0, l0); splitf(sc_[2 * j + 1][1], h1, l1);
                ah[2] = packh(h0, h1); al[2] = packh(l0, l1);
                splitf(sc_[2 * j + 1][2], h0, l0); splitf(sc_[2 * j + 1][3], h1, l1);
                ah[3] = packh(h0, h1); al[3] = packh(l0, l1);
            }
            unsigned vh[4][4], vl[4][4];
#pragma unroll
            for (int p = 0; p < 4; p++) {
                unsigned off = sb + 2 * A_ARR + j * 16 * ALD + p * 16 + vbase;
                ldsm_x4t(vh[p], smb + off * 2);
                ldsm_x4t(vl[p], smb + (off + A_ARR) * 2);
            }
#pragma unroll
            for (int ni = 0; ni < 8; ni++) {
                const int p = ni >> 1, ix = (ni & 1) * 2;
                unsigned b0h = vh[p][ix], b1h = vh[p][ix + 1];
                unsigned b0l = vl[p][ix], b1l = vl[p][ix + 1];
                mma16816(o[ni], ah, b0h, b1h);
                mma16816(o[ni], ah, b0l, b1l);
                mma16816(o[ni], al, b0h, b1h);
            }
        }
    }

    // ---- finalize -> hi/lo bf16 context ----
    float inv0 = 1.f / l0v, inv1 = 1.f / l1v;
    int bb = bh >> 4, hh = bh & 15;
    int q0 = qt * 128 + w * 16 + g;
#pragma unroll
    for (int ni = 0; ni < 8; ni++) {
        int d = ni * 8 + tg * 2;
        size_t i0 = ((size_t)(bb * S_ + q0)) * D_ + hh * 64 + d;
        size_t i1 = ((size_t)(bb * S_ + q0 + 8)) * D_ + hh * 64 + d;
        __nv_bfloat16 h0, l0, h1, l1;
        splitf(o[ni][0] * inv0, h0, l0); splitf(o[ni][1] * inv0, h1, l1);
        *(unsigned*)&Ch[i0] = packh(h0, h1);
        *(unsigned*)&Cl[i0] = packh(l0, l1);
        splitf(o[ni][2] * inv1, h0, l0); splitf(o[ni][3] * inv1, h1, l1);
        *(unsigned*)&Ch[i1] = packh(h0, h1);
        *(unsigned*)&Cl[i1] = packh(l0, l1);
    }
}

// ============================================================================
// Launch
// ============================================================================
extern "C" void kernel_launch(void* const* d_in, const int* in_sizes, int n_in,
                              void* d_out, int out_size)
{
    const float* q  = (const float*)d_in[0];
    const float* k  = (const float*)d_in[1];
    const float* v  = (const float*)d_in[2];
    const float* wq = (const float*)d_in[4];
    const float* bq = (const float*)d_in[5];
    const float* wk = (const float*)d_in[6];
    const float* bk = (const float*)d_in[7];
    const float* wv = (const float*)d_in[8];
    const float* bv = (const float*)d_in[9];
    const float* wo = (const float*)d_in[10];
    const float* bo = (const float*)d_in[11];
    float* out = (float*)d_out;

    __nv_bfloat16 *gxh, *gxl, *gwh, *gwl, *gh, *gl, *gch, *gcl;
    cudaGetSymbolAddress((void**)&gxh, g_xh);
    cudaGetSymbolAddress((void**)&gxl, g_xl);
    cudaGetSymbolAddress((void**)&gwh, g_wh);
    cudaGetSymbolAddress((void**)&gwl, g_wl);
    cudaGetSymbolAddress((void**)&gh,  g_h);
    cudaGetSymbolAddress((void**)&gl,  g_l);
    cudaGetSymbolAddress((void**)&gch, g_ch);
    cudaGetSymbolAddress((void**)&gcl, g_cl);

    cudaFuncSetAttribute(gemm_kernel<0>,
                         cudaFuncAttributeMaxDynamicSharedMemorySize, GEMM_SMEM);
    cudaFuncSetAttribute(gemm_kernel<1>,
                         cudaFuncAttributeMaxDynamicSharedMemorySize, GEMM_SMEM);
    cudaFuncSetAttribute(attn_kernel,
                         cudaFuncAttributeMaxDynamicSharedMemorySize, ATTN_SMEM);

    // 1) split inputs + weights to bf16 hi/lo
    convert_kernel<<<16384, 256>>>(q, k, v, wq, wk, wv, wo);

    // 2) QKV projections
    gemm_kernel<0><<<dim3(8, 32, 3), 256, GEMM_SMEM>>>(
        gxh, gxl, gwh, gwl, bq, bk, bv, gh, gl, nullptr);

    // 3) attention
    attn_kernel<<<dim3(S_ / 128, B_ * H_), 256, ATTN_SMEM>>>(gh, gl, gch, gcl);

    // 4) output projection
    gemm_kernel<1><<<dim3(8, 32, 1), 256, GEMM_SMEM>>>(
        gch, gcl, gwh + 3 * WSZ, gwl + 3 * WSZ, bo, bo, bo, nullptr, nullptr, out);
}

// round 8
// speedup vs baseline: 1.6736x; 1.0722x over previous
#include <cuda_runtime.h>
#include <cuda_bf16.h>
#include <cstdint>

#define DINLINE __device__ __forceinline__

constexpr int B_  = 2;
constexpr int S_  = 2048;
constexpr int D_  = 1024;
constexpr int H_  = 16;
constexpr int DK_ = 64;

constexpr size_t NQKV = (size_t)B_ * H_ * S_ * DK_;   // 4M elems
constexpr size_t XSZ  = (size_t)4096 * 1024;          // 4M
constexpr size_t WSZ  = (size_t)1024 * 1024;          // 1M

// ---------------- global scratch ----------------
__device__ __nv_bfloat16 g_xh[3 * XSZ], g_xl[3 * XSZ];     // q,k,v inputs split
__device__ __nv_bfloat16 g_wh[4 * WSZ], g_wl[4 * WSZ];     // wq,wk,wv,wo split
__device__ __nv_bfloat16 g_h[3 * NQKV], g_l[3 * NQKV];     // Q,K,V proj [B,H,S,DK]
__device__ __nv_bfloat16 g_ch[XSZ], g_cl[XSZ];             // attn context split

// ---------------- helpers ----------------
DINLINE unsigned packh(__nv_bfloat16 a, __nv_bfloat16 b) {
    __nv_bfloat162 v; v.x = a; v.y = b;
    return *reinterpret_cast<unsigned*>(&v);
}
DINLINE void splitf(float x, __nv_bfloat16& h, __nv_bfloat16& l) {
    h = __float2bfloat16(x);
    l = __float2bfloat16(x - __bfloat162float(h));
}
DINLINE void mma16816(float* c, const unsigned* a, unsigned b0, unsigned b1) {
    asm volatile(
        "mma.sync.aligned.m16n8k16.row.col.f32.bf16.bf16.f32 "
        "{%0,%1,%2,%3},{%4,%5,%6,%7},{%8,%9},{%0,%1,%2,%3};\n"
        : "+f"(c[0]), "+f"(c[1]), "+f"(c[2]), "+f"(c[3])
        : "r"(a[0]), "r"(a[1]), "r"(a[2]), "r"(a[3]), "r"(b0), "r"(b1));
}
DINLINE unsigned smem_u32(const void* p) {
    unsigned a;
    asm("{.reg .u64 t; cvta.to.shared.u64 t, %1; cvt.u32.u64 %0, t;}" : "=r"(a) : "l"(p));
    return a;
}
DINLINE void ldsm_x4(unsigned* r, unsigned addr) {
    asm volatile("ldmatrix.sync.aligned.m8n8.x4.shared.b16 {%0,%1,%2,%3}, [%4];"
                 : "=r"(r[0]), "=r"(r[1]), "=r"(r[2]), "=r"(r[3]) : "r"(addr));
}
DINLINE void ldsm_x4t(unsigned* r, unsigned addr) {
    asm volatile("ldmatrix.sync.aligned.m8n8.x4.trans.shared.b16 {%0,%1,%2,%3}, [%4];"
                 : "=r"(r[0]), "=r"(r[1]), "=r"(r[2]), "=r"(r[3]) : "r"(addr));
}

#define CP_ASYNC16(dst, src) \
    asm volatile("cp.async.cg.shared.global [%0], [%1], 16;\n" :: "r"(dst), "l"(src))
#define CP_COMMIT()  asm volatile("cp.async.commit_group;\n")
#define CP_WAIT0()   asm volatile("cp.async.wait_group 0;\n")
#define CP_WAIT1()   asm volatile("cp.async.wait_group 1;\n")

// ============================================================================
// convert: f32 inputs/weights -> bf16 hi/lo global buffers
// ============================================================================
__global__ void __launch_bounds__(256) convert_kernel(
    const float* __restrict__ q, const float* __restrict__ k, const float* __restrict__ v,
    const float* __restrict__ wq, const float* __restrict__ wk,
    const float* __restrict__ wv, const float* __restrict__ wo)
{
    size_t i = ((size_t)blockIdx.x * 256 + threadIdx.x) * 4;
    const float* src;
    __nv_bfloat16 *dh, *dl;
    size_t off;
    if (i < (size_t)3 * XSZ) {
        int z = (int)(i / XSZ);
        off = i - (size_t)z * XSZ;
        src = (z == 0) ? q : (z == 1) ? k : v;
        dh = g_xh + (size_t)z * XSZ; dl = g_xl + (size_t)z * XSZ;
    } else {
        size_t j = i - (size_t)3 * XSZ;
        int z = (int)(j / WSZ);
        off = j - (size_t)z * WSZ;
        src = (z == 0) ? wq : (z == 1) ? wk : (z == 2) ? wv : wo;
        dh = g_wh + (size_t)z * WSZ; dl = g_wl + (size_t)z * WSZ;
    }
    float4 val = *(const float4*)(src + off);
    __nv_bfloat16 h0, l0, h1, l1, h2, l2, h3, l3;
    splitf(val.x, h0, l0); splitf(val.y, h1, l1);
    splitf(val.z, h2, l2); splitf(val.w, h3, l3);
    uint2 uh = { packh(h0, h1), packh(h2, h3) };
    uint2 ul = { packh(l0, l1), packh(l2, l3) };
    *(uint2*)(dh + off) = uh;
    *(uint2*)(dl + off) = ul;
}

// ============================================================================
// GEMM: Y[4096,1024] = X @ W^T + b, pre-split bf16 hi/lo, 3-term.
// Tile 128x128, 256 threads (8 warps, warptile 32x64), BK=32.
// 3-stage cp.async pipeline with ONE __syncthreads per K-iteration
// (issue kt+2 into stage (kt+2)%3 == the stage computed at kt-1, which the
//  top-of-loop barrier already protects).
// XOR-swizzled smem: 16B chunk (row,c) at byte  row*64 + ((c^((row>>1)&3))<<4)
// -> conflict-free ldmatrix & cp.async, no padding. Stage=32KB, 3 stages=96KB,
// 2 CTAs/SM.
// MODE 0: z selects (X,W,b); hi/lo bf16 out [B,H,S,DK].  MODE 1: f32 out.
// ============================================================================
constexpr int G_ARR_B   = 128 * 64;            // 8192 bytes per array
constexpr int G_STAGE_B = 4 * G_ARR_B;         // 32768 bytes per stage
constexpr int GEMM_SMEM = 3 * G_STAGE_B;       // 98304 bytes

template<int MODE>
__global__ void __launch_bounds__(256, 2) gemm_kernel(
    const __nv_bfloat16* __restrict__ Ahg, const __nv_bfloat16* __restrict__ Alg,
    const __nv_bfloat16* __restrict__ Whg, const __nv_bfloat16* __restrict__ Wlg,
    const float* __restrict__ b0p, const float* __restrict__ b1p, const float* __restrict__ b2p,
    __nv_bfloat16* __restrict__ Yh, __nv_bfloat16* __restrict__ Yl,
    float* __restrict__ Yf)
{
    extern __shared__ __nv_bfloat16 gsm[];
    const unsigned smb = smem_u32(gsm);

    const int z = (MODE == 0) ? blockIdx.z : 0;
    const __nv_bfloat16* Ah = Ahg + (size_t)z * XSZ;
    const __nv_bfloat16* Al = Alg + (size_t)z * XSZ;
    const __nv_bfloat16* Bh = Whg + (size_t)z * WSZ;
    const __nv_bfloat16* Bl = Wlg + (size_t)z * WSZ;
    const float* bias = (z == 0) ? b0p : (z == 1) ? b1p : b2p;

    const int t    = threadIdx.x;
    const int w    = t >> 5;
    const int lane = t & 31;
    const int g    = lane >> 2;
    const int tg   = lane & 3;
    const int lm   = lane >> 3;   // ldmatrix matrix id (0..3)
    const int lr   = lane & 7;    // ldmatrix row-in-matrix
    const int wm   = w >> 1;      // 0..3
    const int wn   = w & 1;       // 0..1
    const int m0   = blockIdx.y * 128;
    const int n0   = blockIdx.x * 128;

    // ldmatrix per-lane bases: byte offset of row + xor key; chunk col base
    unsigned aoff[2], axor[2], boff[4], bxor[4];
    const unsigned aC = (unsigned)(lm >> 1);   // A chunk-col base (0/1)
    const unsigned bC = (unsigned)(lm & 1);    // B chunk-col base (0/1)
#pragma unroll
    for (int mi = 0; mi < 2; mi++) {
        int r = wm * 32 + mi * 16 + ((lm & 1) << 3) + lr;
        aoff[mi] = (unsigned)r * 64u;
        axor[mi] = (unsigned)((r >> 1) & 3);
    }
#pragma unroll
    for (int p = 0; p < 4; p++) {
        int r = wn * 64 + p * 16 + ((lm >> 1) << 3) + lr;
        boff[p] = (unsigned)r * 64u;
        bxor[p] = (unsigned)((r >> 1) & 3);
    }

    float acc[2][8][4];
#pragma unroll
    for (int mi = 0; mi < 2; mi++)
#pragma unroll
        for (int ni = 0; ni < 8; ni++)
#pragma unroll
            for (int j = 0; j < 4; j++) acc[mi][ni][j] = 0.f;

    auto issue_stage = [&](int kt, int stg) {
        const unsigned base = (unsigned)(stg * G_STAGE_B);
#pragma unroll
        for (int i = 0; i < 8; i++) {
            int id = t + i * 256;
            int a_ = id >> 9;                 // array 0..3
            int cid = id & 511;
            int row = cid >> 2, c = cid & 3;
            const __nv_bfloat16* gp =
                (a_ == 0) ? Ah : (a_ == 1) ? Al : (a_ == 2) ? Bh : Bl;
            const int r0 = (a_ < 2) ? m0 : n0;
            unsigned dst = smb + base + (unsigned)a_ * G_ARR_B
                         + (unsigned)row * 64u
                         + ((unsigned)(c ^ ((row >> 1) & 3)) << 4);
            CP_ASYNC16(dst, gp + (size_t)(r0 + row) * 1024 + (size_t)kt * 32 + c * 8);
        }
        CP_COMMIT();
    };

    issue_stage(0, 0);
    issue_stage(1, 1);

    for (int kt = 0; kt < 32; kt++) {
        if (kt < 31) CP_WAIT1(); else CP_WAIT0();
        __syncthreads();          // tile kt ready AND compute of kt-1 done

        if (kt + 2 < 32) issue_stage(kt + 2, (kt + 2) % 3);

        const unsigned sb = smb + (unsigned)((kt % 3) * G_STAGE_B);
#pragma unroll
        for (int kk2 = 0; kk2 < 2; kk2++) {      // kk = kk2*16 -> chunk +2*kk2
            unsigned ah[2][4], al[2][4], bh[4][4], bl[4][4];
#pragma unroll
            for (int mi = 0; mi < 2; mi++) {
                unsigned cidx = (((unsigned)(2 * kk2) + aC) ^ axor[mi]) << 4;
                ldsm_x4(ah[mi], sb + aoff[mi] + cidx);
                ldsm_x4(al[mi], sb + G_ARR_B + aoff[mi] + cidx);
            }
#pragma unroll
            for (int p = 0; p < 4; p++) {
                unsigned cidx = (((unsigned)(2 * kk2) + bC) ^ bxor[p]) << 4;
                ldsm_x4(bh[p], sb + 2 * G_ARR_B + boff[p] + cidx);
                ldsm_x4(bl[p], sb + 3 * G_ARR_B + boff[p] + cidx);
            }
#pragma unroll
            for (int ni = 0; ni < 8; ni++) {
                const int p = ni >> 1, ix = (ni & 1) * 2;
                unsigned b0h = bh[p][ix], b1h = bh[p][ix + 1];
                unsigned b0l = bl[p][ix], b1l = bl[p][ix + 1];
#pragma unroll
                for (int mi = 0; mi < 2; mi++) {
                    mma16816(acc[mi][ni], ah[mi], b0h, b1h);
                    mma16816(acc[mi][ni], ah[mi], b0l, b1l);
                    mma16816(acc[mi][ni], al[mi], b0h, b1h);
                }
            }
        }
    }

    // ---- epilogue ----
    const size_t zoff = (size_t)z * NQKV;
#pragma unroll
    for (int mi = 0; mi < 2; mi++) {
#pragma unroll
        for (int ni = 0; ni < 8; ni++) {
            int r = m0 + wm * 32 + mi * 16 + g;
            int c = n0 + wn * 64 + ni * 8 + tg * 2;
            float b0 = bias[c], b1 = bias[c + 1];
            float v00 = acc[mi][ni][0] + b0;
            float v01 = acc[mi][ni][1] + b1;
            float v10 = acc[mi][ni][2] + b0;
            float v11 = acc[mi][ni][3] + b1;
            if (MODE == 0) {
                int bb = r >> 11, ss = r & 2047;
                int hh = c >> 6, d = c & 63;
                size_t i0 = zoff + ((size_t)(bb * H_ + hh) * S_ + ss) * DK_ + d;
                size_t i1 = zoff + ((size_t)(bb * H_ + hh) * S_ + (ss + 8)) * DK_ + d;
                __nv_bfloat16 h0, l0, h1, l1;
                splitf(v00, h0, l0); splitf(v01, h1, l1);
                *(unsigned*)&Yh[i0] = packh(h0, h1);
                *(unsigned*)&Yl[i0] = packh(l0, l1);
                splitf(v10, h0, l0); splitf(v11, h1, l1);
                *(unsigned*)&Yh[i1] = packh(h0, h1);
                *(unsigned*)&Yl[i1] = packh(l0, l1);
            } else {
                Yf[(size_t)r * 1024 + c]           = v00;
                Yf[(size_t)r * 1024 + c + 1]       = v01;
                Yf[(size_t)(r + 8) * 1024 + c]     = v10;
                Yf[(size_t)(r + 8) * 1024 + c + 1] = v11;
            }
        }
    }
}

// ============================================================================
// Flash attention (causal), DK=64, Q-tile 128 (8 warps x 16 rows), KV-tile 64.
// K AND V stream row-major [kv][dk] via cp.async double buffer.
// K frags: ldmatrix.x4;  V frags: ldmatrix.x4.trans (free transpose).
// qt REVERSED so heavy CTAs launch first (wave load balance).
// ============================================================================
constexpr int ALD = 72;
constexpr int A_ARR = 64 * ALD;         // 4608 elems per array
constexpr int STAGE = 4 * A_ARR;        // Kh,Kl,Vh,Vl
constexpr int ATTN_SMEM = 2 * STAGE * 2;

__global__ void __launch_bounds__(256, 1) attn_kernel(
    const __nv_bfloat16* __restrict__ Gh, const __nv_bfloat16* __restrict__ Gl,
    __nv_bfloat16* __restrict__ Ch, __nv_bfloat16* __restrict__ Cl)
{
    extern __shared__ __nv_bfloat16 sm[];

    const int qt   = (int)gridDim.x - 1 - (int)blockIdx.x;  // heavy first
    const int bh   = blockIdx.y;
    const int t    = threadIdx.x;
    const int w    = t >> 5;
    const int lane = t & 31;
    const int g    = lane >> 2;
    const int tg   = lane & 3;
    const int lm   = lane >> 3;
    const int lr   = lane & 7;

    const size_t hb = (size_t)bh * S_ * DK_;
    const __nv_bfloat16* Qhb = Gh + hb;
    const __nv_bfloat16* Qlb = Gl + hb;
    const __nv_bfloat16* Khb = Gh + NQKV + hb;
    const __nv_bfloat16* Klb = Gl + NQKV + hb;
    const __nv_bfloat16* Vhb = Gh + 2 * NQKV + hb;
    const __nv_bfloat16* Vlb = Gl + 2 * NQKV + hb;

    const unsigned smb = smem_u32(sm);
    const float NEG = -1e30f;

    // ldmatrix per-lane bases (element offsets)
    const int kbase = lr * ALD + (lm << 3);                        // K (non-trans)
    const int vbase = (((lm & 1) << 3) + lr) * ALD + ((lm >> 1) << 3);  // V (trans)

    // ---- Q fragments straight from global ----
    unsigned qh[4][4], ql[4][4];
    {
        size_t r0 = (size_t)(qt * 128 + w * 16 + g) * DK_;
        size_t r1 = r0 + 8 * DK_;
#pragma unroll
        for (int kk = 0; kk < 4; kk++) {
            int c = kk * 16 + tg * 2;
            qh[kk][0] = *(const unsigned*)&Qhb[r0 + c];
            qh[kk][1] = *(const unsigned*)&Qhb[r1 + c];
            qh[kk][2] = *(const unsigned*)&Qhb[r0 + c + 8];
            qh[kk][3] = *(const unsigned*)&Qhb[r1 + c + 8];
            ql[kk][0] = *(const unsigned*)&Qlb[r0 + c];
            ql[kk][1] = *(const unsigned*)&Qlb[r1 + c];
            ql[kk][2] = *(const unsigned*)&Qlb[r0 + c + 8];
            ql[kk][3] = *(const unsigned*)&Qlb[r1 + c + 8];
        }
    }

    // stream K+V tiles: 4 arrays x 64 rows x 8 chunks = 2048 chunks, 8/thread
    auto issue_tile = [&](int kt, int stg) {
#pragma unroll
        for (int i = 0; i < 8; i++) {
            int id = t + i * 256;
            int a_ = id >> 9;
            int cid = id & 511;
            int row = cid >> 3, seg = cid & 7;
            const __nv_bfloat16* gp =
                (a_ == 0) ? Khb : (a_ == 1) ? Klb : (a_ == 2) ? Vhb : Vlb;
            unsigned dst = smb + (unsigned)(stg * STAGE + a_ * A_ARR + row * ALD + seg * 8) * 2;
            CP_ASYNC16(dst, gp + (size_t)(kt * 64 + row) * DK_ + seg * 8);
        }
        CP_COMMIT();
    };

    float m0v = NEG, m1v = NEG, l0v = 0.f, l1v = 0.f;
    float o[8][4];
#pragma unroll
    for (int ni = 0; ni < 8; ni++)
#pragma unroll
        for (int j = 0; j < 4; j++) o[ni][j] = 0.f;

    const int ktmax = 2 * qt + 2;
    issue_tile(0, 0);

    for (int kt = 0; kt < ktmax; kt++) {
        const int s = kt & 1;
        CP_WAIT0();
        __syncthreads();

        if (kt + 1 < ktmax) issue_tile(kt + 1, s ^ 1);

        const unsigned sb = (unsigned)(s * STAGE);

        // ---- S = Q K^T ----
        float sc_[8][4];
#pragma unroll
        for (int ni = 0; ni < 8; ni++) {
#pragma unroll
            for (int j = 0; j < 4; j++) sc_[ni][j] = 0.f;
            unsigned kh[2][4], kl[2][4];
#pragma unroll
            for (int q = 0; q < 2; q++) {
                unsigned off = sb + ni * 8 * ALD + q * 32 + kbase;
                ldsm_x4(kh[q], smb + off * 2);
                ldsm_x4(kl[q], smb + (off + A_ARR) * 2);
            }
#pragma unroll
            for (int kk = 0; kk < 4; kk++) {
                const int q = kk >> 1, ix = (kk & 1) * 2;
                unsigned b0h = kh[q][ix], b1h = kh[q][ix + 1];
                unsigned b0l = kl[q][ix], b1l = kl[q][ix + 1];
                mma16816(sc_[ni], qh[kk], b0h, b1h);
                mma16816(sc_[ni], qh[kk], b0l, b1l);
                mma16816(sc_[ni], ql[kk], b0h, b1h);
            }
        }

        // ---- scale + causal mask ----
        const float scale = 0.125f;
        const int rA = qt * 128 + w * 16 + g;
        const int rB = rA + 8;
        if (kt * 64 + 63 > qt * 128 + w * 16) {
#pragma unroll
            for (int ni = 0; ni < 8; ni++) {
                int c0 = kt * 64 + ni * 8 + tg * 2;
                sc_[ni][0] = (c0     > rA) ? NEG : sc_[ni][0] * scale;
                sc_[ni][1] = (c0 + 1 > rA) ? NEG : sc_[ni][1] * scale;
                sc_[ni][2] = (c0     > rB) ? NEG : sc_[ni][2] * scale;
                sc_[ni][3] = (c0 + 1 > rB) ? NEG : sc_[ni][3] * scale;
            }
        } else {
#pragma unroll
            for (int ni = 0; ni < 8; ni++)
#pragma unroll
                for (int j = 0; j < 4; j++) sc_[ni][j] *= scale;
        }

        // ---- streaming softmax ----
        float mx0 = NEG, mx1 = NEG;
#pragma unroll
        for (int ni = 0; ni < 8; ni++) {
            mx0 = fmaxf(mx0, fmaxf(sc_[ni][0], sc_[ni][1]));
            mx1 = fmaxf(mx1, fmaxf(sc_[ni][2], sc_[ni][3]));
        }
        mx0 = fmaxf(mx0, __shfl_xor_sync(0xffffffffu, mx0, 1));
        mx0 = fmaxf(mx0, __shfl_xor_sync(0xffffffffu, mx0, 2));
        mx1 = fmaxf(mx1, __shfl_xor_sync(0xffffffffu, mx1, 1));
        mx1 = fmaxf(mx1, __shfl_xor_sync(0xffffffffu, mx1, 2));

        float nm0 = fmaxf(m0v, mx0), nm1 = fmaxf(m1v, mx1);
        float corr0 = __expf(m0v - nm0), corr1 = __expf(m1v - nm1);

        float sum0 = 0.f, sum1 = 0.f;
#pragma unroll
        for (int ni = 0; ni < 8; ni++) {
            sc_[ni][0] = __expf(sc_[ni][0] - nm0);
            sc_[ni][1] = __expf(sc_[ni][1] - nm0);
            sc_[ni][2] = __expf(sc_[ni][2] - nm1);
            sc_[ni][3] = __expf(sc_[ni][3] - nm1);
            sum0 += sc_[ni][0] + sc_[ni][1];
            sum1 += sc_[ni][2] + sc_[ni][3];
        }
        sum0 += __shfl_xor_sync(0xffffffffu, sum0, 1);
        sum0 += __shfl_xor_sync(0xffffffffu, sum0, 2);
        sum1 += __shfl_xor_sync(0xffffffffu, sum1, 1);
        sum1 += __shfl_xor_sync(0xffffffffu, sum1, 2);

        l0v = l0v * corr0 + sum0;
        l1v = l1v * corr1 + sum1;
        m0v = nm0; m1v = nm1;

#pragma unroll
        for (int ni = 0; ni < 8; ni++) {
            o[ni][0] *= corr0; o[ni][1] *= corr0;
            o[ni][2] *= corr1; o[ni][3] *= corr1;
        }

        // ---- O += P V  (V frags via ldmatrix.trans) ----
#pragma unroll
        for (int j = 0; j < 4; j++) {
            unsigned ah[4], al[4];
            {
                __nv_bfloat16 h0, l0, h1, l1;
                splitf(sc_[2 * j][0], h0, l0); splitf(sc_[2 * j][1], h1, l1);
                ah[0] = packh(h0, h1); al[0] = packh(l0, l1);
                splitf(sc_[2 * j][2], h0, l0); splitf(sc_[2 * j][3], h1, l1);
                ah[1] = packh(h0, h1); al[1] = packh(l0, l1);
                splitf(sc_[2 * j + 1][0], h0, l0); splitf(sc_[2 * j + 1][1], h1, l1);
                ah[2] = packh(h0, h1); al[2] = packh(l0, l1);
                splitf(sc_[2 * j + 1][2], h0, l0); splitf(sc_[2 * j + 1][3], h1, l1);
                ah[3] = packh(h0, h1); al[3] = packh(l0, l1);
            }
            unsigned vh[4][4], vl[4][4];
#pragma unroll
            for (int p = 0; p < 4; p++) {
                unsigned off = sb + 2 * A_ARR + j * 16 * ALD + p * 16 + vbase;
                ldsm_x4t(vh[p], smb + off * 2);
                ldsm_x4t(vl[p], smb + (off + A_ARR) * 2);
            }
#pragma unroll
            for (int ni = 0; ni < 8; ni++) {
                const int p = ni >> 1, ix = (ni & 1) * 2;
                unsigned b0h = vh[p][ix], b1h = vh[p][ix + 1];
                unsigned b0l = vl[p][ix], b1l = vl[p][ix + 1];
                mma16816(o[ni], ah, b0h, b1h);
                mma16816(o[ni], ah, b0l, b1l);
                mma16816(o[ni], al, b0h, b1h);
            }
        }
    }

    // ---- finalize -> hi/lo bf16 context ----
    float inv0 = 1.f / l0v, inv1 = 1.f / l1v;
    int bb = bh >> 4, hh = bh & 15;
    int q0 = qt * 128 + w * 16 + g;
#pragma unroll
    for (int ni = 0; ni < 8; ni++) {
        int d = ni * 8 + tg * 2;
        size_t i0 = ((size_t)(bb * S_ + q0)) * D_ + hh * 64 + d;
        size_t i1 = ((size_t)(bb * S_ + q0 + 8)) * D_ + hh * 64 + d;
        __nv_bfloat16 h0, l0, h1, l1;
        splitf(o[ni][0] * inv0, h0, l0); splitf(o[ni][1] * inv0, h1, l1);
        *(unsigned*)&Ch[i0] = packh(h0, h1);
        *(unsigned*)&Cl[i0] = packh(l0, l1);
        splitf(o[ni][2] * inv1, h0, l0); splitf(o[ni][3] * inv1, h1, l1);
        *(unsigned*)&Ch[i1] = packh(h0, h1);
        *(unsigned*)&Cl[i1] = packh(l0, l1);
    }
}

// ============================================================================
// Launch
// ============================================================================
extern "C" void kernel_launch(void* const* d_in, const int* in_sizes, int n_in,
                              void* d_out, int out_size)
{
    const float* q  = (const float*)d_in[0];
    const float* k  = (const float*)d_in[1];
    const float* v  = (const float*)d_in[2];
    const float* wq = (const float*)d_in[4];
    const float* bq = (const float*)d_in[5];
    const float* wk = (const float*)d_in[6];
    const float* bk = (const float*)d_in[7];
    const float* wv = (const float*)d_in[8];
    const float* bv = (const float*)d_in[9];
    const float* wo = (const float*)d_in[10];
    const float* bo = (const float*)d_in[11];
    float* out = (float*)d_out;

    __nv_bfloat16 *gxh, *gxl, *gwh, *gwl, *gh, *gl, *gch, *gcl;
    cudaGetSymbolAddress((void**)&gxh, g_xh);
    cudaGetSymbolAddress((void**)&gxl, g_xl);
    cudaGetSymbolAddress((void**)&gwh, g_wh);
    cudaGetSymbolAddress((void**)&gwl, g_wl);
    cudaGetSymbolAddress((void**)&gh,  g_h);
    cudaGetSymbolAddress((void**)&gl,  g_l);
    cudaGetSymbolAddress((void**)&gch, g_ch);
    cudaGetSymbolAddress((void**)&gcl, g_cl);

    cudaFuncSetAttribute(gemm_kernel<0>,
                         cudaFuncAttributeMaxDynamicSharedMemorySize, GEMM_SMEM);
    cudaFuncSetAttribute(gemm_kernel<1>,
                         cudaFuncAttributeMaxDynamicSharedMemorySize, GEMM_SMEM);
    cudaFuncSetAttribute(attn_kernel,
                         cudaFuncAttributeMaxDynamicSharedMemorySize, ATTN_SMEM);

    // 1) split inputs + weights to bf16 hi/lo
    convert_kernel<<<16384, 256>>>(q, k, v, wq, wk, wv, wo);

    // 2) QKV projections
    gemm_kernel<0><<<dim3(8, 32, 3), 256, GEMM_SMEM>>>(
        gxh, gxl, gwh, gwl, bq, bk, bv, gh, gl, nullptr);

    // 3) attention
    attn_kernel<<<dim3(S_ / 128, B_ * H_), 256, ATTN_SMEM>>>(gh, gl, gch, gcl);

    // 4) output projection
    gemm_kernel<1><<<dim3(8, 32, 1), 256, GEMM_SMEM>>>(
        gch, gcl, gwh + 3 * WSZ, gwl + 3 * WSZ, bo, bo, bo, nullptr, nullptr, out);
}